// round 11
// baseline (speedup 1.0000x reference)
#include <cuda_runtime.h>
#include <cuda_bf16.h>
#include <cstdint>

// ===========================================================================
// LinearAttention via mma.sync bf16 split-precision.
// R11: ctx moved to tensor pipe. kv GEMM epilogue writes exp(K)/V as bf16
//      hi/lo; ctx_mma computes C = expK @ V^T (K=4096) per (b,h) with a
//      ones-column producing row sums for free. fp32 g_kv eliminated.
// ===========================================================================

#define NB   16
#define NPIX 4096
#define CD   256
#define KD   256

__device__ __nv_bfloat16 g_xt_hi[(long)NB * NPIX * CD];
__device__ __nv_bfloat16 g_xt_lo[(long)NB * NPIX * CD];
__device__ __nv_bfloat16 g_wkv_hi[512 * KD];
__device__ __nv_bfloat16 g_wkv_lo[512 * KD];
__device__ __nv_bfloat16 g_wqt_hi[CD * KD];
__device__ __nv_bfloat16 g_wqt_lo[CD * KD];
__device__ __nv_bfloat16 g_ekv_hi[(long)NB * 512 * NPIX];  // exp(K) rows 0-255, V rows 256-511
__device__ __nv_bfloat16 g_ekv_lo[(long)NB * 512 * NPIX];
__device__ float g_C[NB * 8 * 32 * 33];                    // C[32x32] + S col at 32
__device__ __nv_bfloat16 g_u_hi[NB * CD * KD];
__device__ __nv_bfloat16 g_u_lo[NB * CD * KD];
__device__ __nv_bfloat16 g_weff_hi[NB * CD * KD];
__device__ __nv_bfloat16 g_weff_lo[NB * CD * KD];

// ------------------------- helpers ----------------------------------------
__device__ __forceinline__ uint32_t smem_u32(const void* p) {
    uint32_t a;
    asm("{ .reg .u64 t; cvta.to.shared.u64 t, %1; cvt.u32.u64 %0, t; }"
        : "=r"(a) : "l"(p));
    return a;
}
__device__ __forceinline__ void ldsm_x4(uint32_t* r, uint32_t addr) {
    asm volatile("ldmatrix.sync.aligned.m8n8.x4.shared.b16 {%0,%1,%2,%3}, [%4];"
                 : "=r"(r[0]), "=r"(r[1]), "=r"(r[2]), "=r"(r[3]) : "r"(addr));
}
__device__ __forceinline__ void mma_bf16(float* d, const uint32_t* a, const uint32_t* b) {
    asm volatile(
        "mma.sync.aligned.m16n8k16.row.col.f32.bf16.bf16.f32 "
        "{%0,%1,%2,%3}, {%4,%5,%6,%7}, {%8,%9}, {%0,%1,%2,%3};"
        : "+f"(d[0]), "+f"(d[1]), "+f"(d[2]), "+f"(d[3])
        : "r"(a[0]), "r"(a[1]), "r"(a[2]), "r"(a[3]), "r"(b[0]), "r"(b[1]));
}
__device__ __forceinline__ void cp_async16(uint32_t smem_dst, const void* gsrc) {
    asm volatile("cp.async.ca.shared.global [%0], [%1], 16;"
                 :: "r"(smem_dst), "l"(gsrc) : "memory");
}
__device__ __forceinline__ void cp_commit() {
    asm volatile("cp.async.commit_group;" ::: "memory");
}
template <int N>
__device__ __forceinline__ void cp_wait() {
    asm volatile("cp.async.wait_group %0;" :: "n"(N) : "memory");
}
__device__ __forceinline__ void split_bf16(float v, __nv_bfloat16& hi, __nv_bfloat16& lo) {
    hi = __float2bfloat16(v);
    lo = __float2bfloat16(v - __bfloat162float(hi));
}

// ------------------------- conversion kernels ------------------------------
__global__ void __launch_bounds__(256) conv_x(const float* __restrict__ x) {
    __shared__ float sb[32][257];
    const int b = blockIdx.y, n0 = blockIdx.x * 32;
    const float* xb = x + (long)b * CD * NPIX;
    const int tn = threadIdx.x & 31, tc = threadIdx.x >> 5;

#pragma unroll
    for (int c0 = 0; c0 < 256; c0 += 8) {
        sb[tn][c0 + tc] = xb[(long)(c0 + tc) * NPIX + n0 + tn];
    }
    __syncthreads();

    const long base = (long)b * NPIX * CD;
    const int c = threadIdx.x;
#pragma unroll 4
    for (int i = 0; i < 32; i++) {
        float v = sb[i][c];
        __nv_bfloat16 hi, lo;
        split_bf16(v, hi, lo);
        long idx = base + (long)(n0 + i) * CD + c;
        g_xt_hi[idx] = hi;
        g_xt_lo[idx] = lo;
    }
}

__global__ void __launch_bounds__(256) conv_wkv(const float* __restrict__ w_qkv) {
    int i = blockIdx.x * 256 + threadIdx.x;
    float v = w_qkv[256 * 256 + i];
    __nv_bfloat16 hi, lo;
    split_bf16(v, hi, lo);
    g_wkv_hi[i] = hi;
    g_wkv_lo[i] = lo;
}

__global__ void __launch_bounds__(256) conv_wqt(const float* __restrict__ w_qkv) {
    __shared__ float t[32][33];
    const int t0 = blockIdx.x * 32, c0 = blockIdx.y * 32;
    const int tn = threadIdx.x & 31, tr = threadIdx.x >> 5;
#pragma unroll
    for (int i = 0; i < 32; i += 8)
        t[tr + i][tn] = w_qkv[(long)(t0 + tr + i) * 256 + c0 + tn];
    __syncthreads();
#pragma unroll
    for (int i = 0; i < 32; i += 8) {
        float v = t[tn][tr + i];
        __nv_bfloat16 hi, lo;
        split_bf16(v, hi, lo);
        long idx = (long)(c0 + tr + i) * KD + t0 + tn;
        g_wqt_hi[idx] = hi;
        g_wqt_lo[idx] = lo;
    }
}

// ------------------------- warp-MMA GEMM (cp.async 2-stage) ----------------
// Block tile 128x128, BK=32, 8 warps of 64x32.
// OUT_MODE 0: fp32 (+bias). 1: bf16 hi/lo. 2: bf16 hi/lo with exp() on rows<256.
#define BK   32
#define LDS  40
#define TILE_ELE (128 * LDS)
#define STAGE_ELE (4 * TILE_ELE)
#define SMEM_BYTES (2 * STAGE_ELE * 2)

template <int OUT_MODE>
__global__ void __launch_bounds__(256, 2) gemm_mma(
    const __nv_bfloat16* __restrict__ Ahi, const __nv_bfloat16* __restrict__ Alo, long sA,
    const __nv_bfloat16* __restrict__ Bhi, const __nv_bfloat16* __restrict__ Blo, long sB,
    float* __restrict__ Cf, __nv_bfloat16* __restrict__ Chi, __nv_bfloat16* __restrict__ Clo,
    long sC, int ldc, const float* __restrict__ bias)
{
    extern __shared__ __align__(16) __nv_bfloat16 sm[];

    const int tid = threadIdx.x, wid = tid >> 5, lane = tid & 31;
    const int warp_m = wid >> 2, warp_n = wid & 3;
    const int b = blockIdx.z;
    const int m0 = blockIdx.y * 128, n0 = blockIdx.x * 128;

    const __nv_bfloat16* srcs[4] = {
        Ahi + (long)b * sA + (long)m0 * KD,
        Alo + (long)b * sA + (long)m0 * KD,
        Bhi + (long)b * sB + (long)n0 * KD,
        Blo + (long)b * sB + (long)n0 * KD};

    const uint32_t smb = smem_u32(sm);

    const int ldrow = tid >> 1;
    const int ldseg = (tid & 1) * 8;

    auto prefetch = [&](int kc, int stage) {
        const int k0 = kc * BK;
        const uint32_t sbase = smb + (uint32_t)stage * STAGE_ELE * 2;
#pragma unroll
        for (int t4 = 0; t4 < 4; t4++) {
            const __nv_bfloat16* s = srcs[t4] + (long)ldrow * KD + k0 + ldseg;
            const uint32_t d = sbase + (uint32_t)(t4 * TILE_ELE + ldrow * LDS + ldseg) * 2;
            cp_async16(d, s);
            cp_async16(d + 32, s + 16);
        }
        cp_commit();
    };

    float acc[4][4][4];
#pragma unroll
    for (int i = 0; i < 4; i++)
#pragma unroll
        for (int j = 0; j < 4; j++)
#pragma unroll
            for (int k = 0; k < 4; k++) acc[i][j][k] = 0.0f;

    prefetch(0, 0);

    for (int kc = 0; kc < 8; kc++) {
        cp_wait<0>();
        __syncthreads();
        if (kc + 1 < 8) prefetch(kc + 1, (kc + 1) & 1);

        const uint32_t sbase = smb + (uint32_t)(kc & 1) * STAGE_ELE * 2;
#pragma unroll
        for (int ks = 0; ks < 2; ks++) {
            const int kk = ks * 16;
            uint32_t ahi[4][4], alo[4][4];
#pragma unroll
            for (int mf = 0; mf < 4; mf++) {
                const int am = warp_m * 64 + mf * 16 + (lane & 15);
                const uint32_t off = (uint32_t)(am * LDS + kk + (lane >> 4) * 8) * 2;
                ldsm_x4(ahi[mf], sbase + (0 * TILE_ELE) * 2 + off);
                ldsm_x4(alo[mf], sbase + (1 * TILE_ELE) * 2 + off);
            }
#pragma unroll
            for (int np = 0; np < 2; np++) {
                uint32_t bhi[4], blo[4];
                const int bn = warp_n * 32 + np * 16 + ((lane & 16) >> 1) + (lane & 7);
                const uint32_t off = (uint32_t)(bn * LDS + kk + (lane & 8)) * 2;
                ldsm_x4(bhi, sbase + (2 * TILE_ELE) * 2 + off);
                ldsm_x4(blo, sbase + (3 * TILE_ELE) * 2 + off);
#pragma unroll
                for (int mf = 0; mf < 4; mf++)
#pragma unroll
                    for (int h = 0; h < 2; h++)
                        mma_bf16(acc[mf][np * 2 + h], ahi[mf], &bhi[h * 2]);
#pragma unroll
                for (int mf = 0; mf < 4; mf++)
#pragma unroll
                    for (int h = 0; h < 2; h++)
                        mma_bf16(acc[mf][np * 2 + h], ahi[mf], &blo[h * 2]);
#pragma unroll
                for (int mf = 0; mf < 4; mf++)
#pragma unroll
                    for (int h = 0; h < 2; h++)
                        mma_bf16(acc[mf][np * 2 + h], alo[mf], &bhi[h * 2]);
            }
        }
        __syncthreads();
    }

    // ---- epilogue ----
#pragma unroll
    for (int mf = 0; mf < 4; mf++) {
        const int row0 = m0 + warp_m * 64 + mf * 16 + (lane >> 2);
#pragma unroll
        for (int half = 0; half < 2; half++) {
            const int m = row0 + half * 8;
            if (OUT_MODE == 0) {
                const float bb = bias ? bias[m] : 0.0f;
                float* dst = Cf + (long)b * sC + (long)m * ldc + n0 + warp_n * 32 + (lane & 3) * 2;
#pragma unroll
                for (int nf = 0; nf < 4; nf++) {
                    float2 v;
                    v.x = acc[mf][nf][half * 2 + 0] + bb;
                    v.y = acc[mf][nf][half * 2 + 1] + bb;
                    *(float2*)(dst + nf * 8) = v;
                }
            } else {
                __nv_bfloat16* dh = Chi + (long)b * sC + (long)m * ldc + n0 + warp_n * 32 + (lane & 3) * 2;
                __nv_bfloat16* dl = Clo + (long)b * sC + (long)m * ldc + n0 + warp_n * 32 + (lane & 3) * 2;
                const bool do_exp = (OUT_MODE == 2) && (m < 256);
#pragma unroll
                for (int nf = 0; nf < 4; nf++) {
#pragma unroll
                    for (int q = 0; q < 2; q++) {
                        float v = acc[mf][nf][half * 2 + q];
                        if (do_exp) v = __expf(v);
                        __nv_bfloat16 hi, lo;
                        split_bf16(v, hi, lo);
                        dh[nf * 8 + q] = hi;
                        dl[nf * 8 + q] = lo;
                    }
                }
            }
        }
    }
}

// ------------------------- ctx via mma --------------------------------------
// Per (b,h): C[32x48] = expK(32x4096) @ Bpad^T where Bpad rows 0-31 = V,
// row 32 = ones (-> row sums S), rows 33-47 = zero. 3-pass bf16 split.
#define CBK 128
#define CLDS 136
#define CA_ELE (32 * CLDS)
#define CB_ELE (48 * CLDS)
#define CSTAGE_ELE (2 * CA_ELE + 2 * CB_ELE)
#define CSMEM_BYTES (2 * CSTAGE_ELE * 2)   // 87,040 B (reduction area aliases)

__global__ void __launch_bounds__(256) ctx_mma() {
    extern __shared__ __align__(16) __nv_bfloat16 csm[];
    const int h = blockIdx.x, b = blockIdx.y;
    const int tid = threadIdx.x, wid = tid >> 5, lane = tid & 31;

    const __nv_bfloat16* srcs[4] = {
        g_ekv_hi + ((long)b * 512 + h * 32) * NPIX,         // expK hi
        g_ekv_lo + ((long)b * 512 + h * 32) * NPIX,         // expK lo
        g_ekv_hi + ((long)b * 512 + 256 + h * 32) * NPIX,   // V hi
        g_ekv_lo + ((long)b * 512 + 256 + h * 32) * NPIX};  // V lo
    const uint32_t offs[4] = {0, CA_ELE, 2 * CA_ELE, 2 * CA_ELE + CB_ELE};

    const uint32_t smb = smem_u32(csm);

    // init constant B rows (32 = ones in hi / zeros in lo; 33-47 = zero)
    const __nv_bfloat16 one = __float2bfloat16(1.0f);
    const __nv_bfloat16 zero = __float2bfloat16(0.0f);
    for (int s = 0; s < 2; s++) {
        __nv_bfloat16* Bh = csm + s * CSTAGE_ELE + 2 * CA_ELE + 32 * CLDS;
        __nv_bfloat16* Bl = csm + s * CSTAGE_ELE + 2 * CA_ELE + CB_ELE + 32 * CLDS;
        for (int i = tid; i < 16 * CLDS; i += 256) {
            Bh[i] = (i < CLDS) ? one : zero;
            Bl[i] = zero;
        }
    }

    const int lrow = tid >> 3;            // 0..31
    const int lseg = (tid & 7) * 16;      // bf16 elements, 2x16B per thread

    auto prefetch = [&](int kc, int stage) {
        const int k0 = kc * CBK;
        const uint32_t sbase = smb + (uint32_t)stage * CSTAGE_ELE * 2;
#pragma unroll
        for (int t4 = 0; t4 < 4; t4++) {
            const __nv_bfloat16* s = srcs[t4] + (long)lrow * NPIX + k0 + lseg;
            const uint32_t d = sbase + (uint32_t)(offs[t4] + lrow * CLDS + lseg) * 2;
            cp_async16(d, s);
            cp_async16(d + 16, s + 8);
        }
        cp_commit();
    };

    float acc[2][6][4];
#pragma unroll
    for (int i = 0; i < 2; i++)
#pragma unroll
        for (int j = 0; j < 6; j++)
#pragma unroll
            for (int k = 0; k < 4; k++) acc[i][j][k] = 0.0f;

    prefetch(0, 0);

    const int kk = wid * 16;   // warp's k-slice within the chunk
    for (int kc = 0; kc < NPIX / CBK; kc++) {
        cp_wait<0>();
        __syncthreads();
        if (kc + 1 < NPIX / CBK) prefetch(kc + 1, (kc + 1) & 1);

        const uint32_t sbase = smb + (uint32_t)(kc & 1) * CSTAGE_ELE * 2;
        uint32_t ahi[2][4], alo[2][4];
#pragma unroll
        for (int mf = 0; mf < 2; mf++) {
            const int am = mf * 16 + (lane & 15);
            const uint32_t off = (uint32_t)(am * CLDS + kk + (lane >> 4) * 8) * 2;
            ldsm_x4(ahi[mf], sbase + off);
            ldsm_x4(alo[mf], sbase + CA_ELE * 2 + off);
        }
#pragma unroll
        for (int np = 0; np < 3; np++) {
            uint32_t bhi[4], blo[4];
            const int bn = np * 16 + ((lane & 16) >> 1) + (lane & 7);
            const uint32_t off = (uint32_t)(bn * CLDS + kk + (lane & 8)) * 2;
            ldsm_x4(bhi, sbase + 2 * CA_ELE * 2 + off);
            ldsm_x4(blo, sbase + (2 * CA_ELE + CB_ELE) * 2 + off);
#pragma unroll
            for (int mf = 0; mf < 2; mf++)
#pragma unroll
                for (int hh = 0; hh < 2; hh++) {
                    float* a = acc[mf][np * 2 + hh];
                    mma_bf16(a, ahi[mf], &bhi[hh * 2]);
                    mma_bf16(a, ahi[mf], &blo[hh * 2]);
                    mma_bf16(a, alo[mf], &bhi[hh * 2]);
                }
        }
        __syncthreads();
    }

    // ---- cross-warp reduction (reuse smem as fp32 [8][32][48]) ----
    float* red = (float*)csm;
#pragma unroll
    for (int mf = 0; mf < 2; mf++)
#pragma unroll
        for (int nf = 0; nf < 6; nf++)
#pragma unroll
            for (int i = 0; i < 4; i++) {
                int row = mf * 16 + (lane >> 2) + (i >> 1) * 8;
                int col = nf * 8 + (lane & 3) * 2 + (i & 1);
                red[((long)wid * 32 + row) * 48 + col] = acc[mf][nf][i];
            }
    __syncthreads();

    float* Cp = g_C + ((long)(b * 8 + h)) * 32 * 33;
    for (int o = tid; o < 32 * 48; o += 256) {
        int row = o / 48, col = o % 48;
        float s = 0.0f;
#pragma unroll
        for (int w = 0; w < 8; w++) s += red[((long)w * 32 + row) * 48 + col];
        if (col < 33) Cp[row * 33 + col] = s;
    }
}

// U = w_out @ blockdiag((C/S)^T), write bf16 hi/lo
__global__ void __launch_bounds__(256) u_kernel(const float* __restrict__ w_out) {
    const int h = blockIdx.x, b = blockIdx.y;
    __shared__ float Cs[32][33];
    __shared__ float s_inv[32];
    const int tid = threadIdx.x;
    const float* Cp = g_C + ((long)(b * 8 + h)) * 32 * 33;

    if (tid < 32) s_inv[tid] = 1.0f / Cp[tid * 33 + 32];
    for (int t = tid; t < 32 * 33; t += 256) Cs[t / 33][t % 33] = Cp[t];
    __syncthreads();

    const int o = tid;
    float wrow[32];
#pragma unroll
    for (int j = 0; j < 32; j += 4)
        *(float4*)&wrow[j] = *(const float4*)&w_out[(long)o * 256 + h * 32 + j];
    float acc[32];
#pragma unroll
    for (int d = 0; d < 32; d++) acc[d] = 0.0f;
#pragma unroll 8
    for (int e = 0; e < 32; e++) {
        float we = wrow[e];
#pragma unroll
        for (int d = 0; d < 32; d++) acc[d] += we * Cs[d][e];
    }
    long ub = (long)b * CD * KD + (long)o * KD + h * 32;
#pragma unroll
    for (int d = 0; d < 32; d++) {
        __nv_bfloat16 hi, lo;
        split_bf16(acc[d] * s_inv[d], hi, lo);
        g_u_hi[ub + d] = hi;
        g_u_lo[ub + d] = lo;
    }
}

// ------------------------- launch ------------------------------------------
extern "C" void kernel_launch(void* const* d_in, const int* in_sizes, int n_in,
                              void* d_out, int out_size)
{
    const float* x     = (const float*)d_in[0];
    const float* w_qkv = (const float*)d_in[1];
    const float* w_out = (const float*)d_in[2];
    const float* b_out = (const float*)d_in[3];
    float* y = (float*)d_out;

    cudaFuncSetAttribute(gemm_mma<0>, cudaFuncAttributeMaxDynamicSharedMemorySize, SMEM_BYTES);
    cudaFuncSetAttribute(gemm_mma<1>, cudaFuncAttributeMaxDynamicSharedMemorySize, SMEM_BYTES);
    cudaFuncSetAttribute(gemm_mma<2>, cudaFuncAttributeMaxDynamicSharedMemorySize, SMEM_BYTES);
    cudaFuncSetAttribute(ctx_mma, cudaFuncAttributeMaxDynamicSharedMemorySize, CSMEM_BYTES);

    __nv_bfloat16 *xt_hi, *xt_lo, *wkv_hi, *wkv_lo, *wqt_hi, *wqt_lo;
    __nv_bfloat16 *u_hi, *u_lo, *weff_hi, *weff_lo, *ekv_hi, *ekv_lo;
    cudaGetSymbolAddress((void**)&xt_hi, g_xt_hi);
    cudaGetSymbolAddress((void**)&xt_lo, g_xt_lo);
    cudaGetSymbolAddress((void**)&wkv_hi, g_wkv_hi);
    cudaGetSymbolAddress((void**)&wkv_lo, g_wkv_lo);
    cudaGetSymbolAddress((void**)&wqt_hi, g_wqt_hi);
    cudaGetSymbolAddress((void**)&wqt_lo, g_wqt_lo);
    cudaGetSymbolAddress((void**)&u_hi, g_u_hi);
    cudaGetSymbolAddress((void**)&u_lo, g_u_lo);
    cudaGetSymbolAddress((void**)&weff_hi, g_weff_hi);
    cudaGetSymbolAddress((void**)&weff_lo, g_weff_lo);
    cudaGetSymbolAddress((void**)&ekv_hi, g_ekv_hi);
    cudaGetSymbolAddress((void**)&ekv_lo, g_ekv_lo);

    // 1) conversions
    conv_x<<<dim3(NPIX / 32, NB), 256>>>(x);
    conv_wkv<<<512, 256>>>(w_qkv);
    conv_wqt<<<dim3(8, 8), 256>>>(w_qkv);

    // 2) ekv = exp/copy(wkv @ xT^T) as bf16 hi/lo (M=512, N=4096 per batch)
    gemm_mma<2><<<dim3(NPIX / 128, 4, NB), 256, SMEM_BYTES>>>(
        wkv_hi, wkv_lo, 0L, xt_hi, xt_lo, (long)NPIX * CD,
        nullptr, ekv_hi, ekv_lo, (long)512 * NPIX, NPIX, nullptr);

    // 3) C (+ row sums via ones-column) = expK @ Vpad^T, tensor-core
    ctx_mma<<<dim3(8, NB), 256, CSMEM_BYTES>>>();

    // 4) normalize + U = w_out @ blockdiag(C^T)
    u_kernel<<<dim3(8, NB), 256>>>(w_out);

    // 5) weff = U @ WqT^T   (M=256, N=256) -> bf16 hi/lo
    gemm_mma<1><<<dim3(2, 2, NB), 256, SMEM_BYTES>>>(
        u_hi, u_lo, (long)CD * KD, wqt_hi, wqt_lo, 0L,
        nullptr, weff_hi, weff_lo, (long)CD * KD, KD, nullptr);

    // 6) y = weff @ xT^T + b_out   (M=256, N=4096 per batch)
    gemm_mma<0><<<dim3(NPIX / 128, 2, NB), 256, SMEM_BYTES>>>(
        weff_hi, weff_lo, (long)CD * KD, xt_hi, xt_lo, (long)NPIX * CD,
        y, nullptr, nullptr, (long)CD * NPIX, NPIX, b_out);
}

// round 12
// speedup vs baseline: 1.3317x; 1.3317x over previous
#include <cuda_runtime.h>
#include <cuda_bf16.h>
#include <cstdint>

// ===========================================================================
// LinearAttention via mma.sync bf16 split-precision.
// R12 = R11 + smem-staged bf16 hi/lo epilogue (coalesced 16B stores replace
//       the scattered 2B stores that caused the R11 kv-GEMM regression).
// ===========================================================================

#define NB   16
#define NPIX 4096
#define CD   256
#define KD   256

__device__ __nv_bfloat16 g_xt_hi[(long)NB * NPIX * CD];
__device__ __nv_bfloat16 g_xt_lo[(long)NB * NPIX * CD];
__device__ __nv_bfloat16 g_wkv_hi[512 * KD];
__device__ __nv_bfloat16 g_wkv_lo[512 * KD];
__device__ __nv_bfloat16 g_wqt_hi[CD * KD];
__device__ __nv_bfloat16 g_wqt_lo[CD * KD];
__device__ __nv_bfloat16 g_ekv_hi[(long)NB * 512 * NPIX];  // exp(K) rows 0-255, V rows 256-511
__device__ __nv_bfloat16 g_ekv_lo[(long)NB * 512 * NPIX];
__device__ float g_C[NB * 8 * 32 * 33];                    // C[32x32] + S col at 32
__device__ __nv_bfloat16 g_u_hi[NB * CD * KD];
__device__ __nv_bfloat16 g_u_lo[NB * CD * KD];
__device__ __nv_bfloat16 g_weff_hi[NB * CD * KD];
__device__ __nv_bfloat16 g_weff_lo[NB * CD * KD];

// ------------------------- helpers ----------------------------------------
__device__ __forceinline__ uint32_t smem_u32(const void* p) {
    uint32_t a;
    asm("{ .reg .u64 t; cvta.to.shared.u64 t, %1; cvt.u32.u64 %0, t; }"
        : "=r"(a) : "l"(p));
    return a;
}
__device__ __forceinline__ void ldsm_x4(uint32_t* r, uint32_t addr) {
    asm volatile("ldmatrix.sync.aligned.m8n8.x4.shared.b16 {%0,%1,%2,%3}, [%4];"
                 : "=r"(r[0]), "=r"(r[1]), "=r"(r[2]), "=r"(r[3]) : "r"(addr));
}
__device__ __forceinline__ void mma_bf16(float* d, const uint32_t* a, const uint32_t* b) {
    asm volatile(
        "mma.sync.aligned.m16n8k16.row.col.f32.bf16.bf16.f32 "
        "{%0,%1,%2,%3}, {%4,%5,%6,%7}, {%8,%9}, {%0,%1,%2,%3};"
        : "+f"(d[0]), "+f"(d[1]), "+f"(d[2]), "+f"(d[3])
        : "r"(a[0]), "r"(a[1]), "r"(a[2]), "r"(a[3]), "r"(b[0]), "r"(b[1]));
}
__device__ __forceinline__ void cp_async16(uint32_t smem_dst, const void* gsrc) {
    asm volatile("cp.async.ca.shared.global [%0], [%1], 16;"
                 :: "r"(smem_dst), "l"(gsrc) : "memory");
}
__device__ __forceinline__ void cp_commit() {
    asm volatile("cp.async.commit_group;" ::: "memory");
}
template <int N>
__device__ __forceinline__ void cp_wait() {
    asm volatile("cp.async.wait_group %0;" :: "n"(N) : "memory");
}
__device__ __forceinline__ void split_bf16(float v, __nv_bfloat16& hi, __nv_bfloat16& lo) {
    hi = __float2bfloat16(v);
    lo = __float2bfloat16(v - __bfloat162float(hi));
}

// ------------------------- conversion kernels ------------------------------
__global__ void __launch_bounds__(256) conv_x(const float* __restrict__ x) {
    __shared__ float sb[32][257];
    const int b = blockIdx.y, n0 = blockIdx.x * 32;
    const float* xb = x + (long)b * CD * NPIX;
    const int tn = threadIdx.x & 31, tc = threadIdx.x >> 5;

#pragma unroll
    for (int c0 = 0; c0 < 256; c0 += 8) {
        sb[tn][c0 + tc] = xb[(long)(c0 + tc) * NPIX + n0 + tn];
    }
    __syncthreads();

    const long base = (long)b * NPIX * CD;
    const int c = threadIdx.x;
#pragma unroll 4
    for (int i = 0; i < 32; i++) {
        float v = sb[i][c];
        __nv_bfloat16 hi, lo;
        split_bf16(v, hi, lo);
        long idx = base + (long)(n0 + i) * CD + c;
        g_xt_hi[idx] = hi;
        g_xt_lo[idx] = lo;
    }
}

__global__ void __launch_bounds__(256) conv_wkv(const float* __restrict__ w_qkv) {
    int i = blockIdx.x * 256 + threadIdx.x;
    float v = w_qkv[256 * 256 + i];
    __nv_bfloat16 hi, lo;
    split_bf16(v, hi, lo);
    g_wkv_hi[i] = hi;
    g_wkv_lo[i] = lo;
}

__global__ void __launch_bounds__(256) conv_wqt(const float* __restrict__ w_qkv) {
    __shared__ float t[32][33];
    const int t0 = blockIdx.x * 32, c0 = blockIdx.y * 32;
    const int tn = threadIdx.x & 31, tr = threadIdx.x >> 5;
#pragma unroll
    for (int i = 0; i < 32; i += 8)
        t[tr + i][tn] = w_qkv[(long)(t0 + tr + i) * 256 + c0 + tn];
    __syncthreads();
#pragma unroll
    for (int i = 0; i < 32; i += 8) {
        float v = t[tn][tr + i];
        __nv_bfloat16 hi, lo;
        split_bf16(v, hi, lo);
        long idx = (long)(c0 + tr + i) * KD + t0 + tn;
        g_wqt_hi[idx] = hi;
        g_wqt_lo[idx] = lo;
    }
}

// ------------------------- warp-MMA GEMM (cp.async 2-stage) ----------------
// Block tile 128x128, BK=32, 8 warps of 64x32.
// OUT_MODE 0: fp32 (+bias). 1: bf16 hi/lo. 2: bf16 hi/lo + exp() on K tiles.
#define BK   32
#define LDS  40
#define TILE_ELE (128 * LDS)
#define STAGE_ELE (4 * TILE_ELE)
#define SMEM_BYTES (2 * STAGE_ELE * 2)   // 81,920 B; epilogue staging fits (69,632 B)

template <int OUT_MODE>
__global__ void __launch_bounds__(256, 2) gemm_mma(
    const __nv_bfloat16* __restrict__ Ahi, const __nv_bfloat16* __restrict__ Alo, long sA,
    const __nv_bfloat16* __restrict__ Bhi, const __nv_bfloat16* __restrict__ Blo, long sB,
    float* __restrict__ Cf, __nv_bfloat16* __restrict__ Chi, __nv_bfloat16* __restrict__ Clo,
    long sC, int ldc, const float* __restrict__ bias)
{
    extern __shared__ __align__(16) __nv_bfloat16 sm[];

    const int tid = threadIdx.x, wid = tid >> 5, lane = tid & 31;
    const int warp_m = wid >> 2, warp_n = wid & 3;
    const int b = blockIdx.z;
    const int m0 = blockIdx.y * 128, n0 = blockIdx.x * 128;

    const __nv_bfloat16* srcs[4] = {
        Ahi + (long)b * sA + (long)m0 * KD,
        Alo + (long)b * sA + (long)m0 * KD,
        Bhi + (long)b * sB + (long)n0 * KD,
        Blo + (long)b * sB + (long)n0 * KD};

    const uint32_t smb = smem_u32(sm);

    const int ldrow = tid >> 1;
    const int ldseg = (tid & 1) * 8;

    auto prefetch = [&](int kc, int stage) {
        const int k0 = kc * BK;
        const uint32_t sbase = smb + (uint32_t)stage * STAGE_ELE * 2;
#pragma unroll
        for (int t4 = 0; t4 < 4; t4++) {
            const __nv_bfloat16* s = srcs[t4] + (long)ldrow * KD + k0 + ldseg;
            const uint32_t d = sbase + (uint32_t)(t4 * TILE_ELE + ldrow * LDS + ldseg) * 2;
            cp_async16(d, s);
            cp_async16(d + 32, s + 16);
        }
        cp_commit();
    };

    float acc[4][4][4];
#pragma unroll
    for (int i = 0; i < 4; i++)
#pragma unroll
        for (int j = 0; j < 4; j++)
#pragma unroll
            for (int k = 0; k < 4; k++) acc[i][j][k] = 0.0f;

    prefetch(0, 0);

    for (int kc = 0; kc < 8; kc++) {
        cp_wait<0>();
        __syncthreads();
        if (kc + 1 < 8) prefetch(kc + 1, (kc + 1) & 1);

        const uint32_t sbase = smb + (uint32_t)(kc & 1) * STAGE_ELE * 2;
#pragma unroll
        for (int ks = 0; ks < 2; ks++) {
            const int kk = ks * 16;
            uint32_t ahi[4][4], alo[4][4];
#pragma unroll
            for (int mf = 0; mf < 4; mf++) {
                const int am = warp_m * 64 + mf * 16 + (lane & 15);
                const uint32_t off = (uint32_t)(am * LDS + kk + (lane >> 4) * 8) * 2;
                ldsm_x4(ahi[mf], sbase + (0 * TILE_ELE) * 2 + off);
                ldsm_x4(alo[mf], sbase + (1 * TILE_ELE) * 2 + off);
            }
#pragma unroll
            for (int np = 0; np < 2; np++) {
                uint32_t bhi[4], blo[4];
                const int bn = warp_n * 32 + np * 16 + ((lane & 16) >> 1) + (lane & 7);
                const uint32_t off = (uint32_t)(bn * LDS + kk + (lane & 8)) * 2;
                ldsm_x4(bhi, sbase + (2 * TILE_ELE) * 2 + off);
                ldsm_x4(blo, sbase + (3 * TILE_ELE) * 2 + off);
#pragma unroll
                for (int mf = 0; mf < 4; mf++)
#pragma unroll
                    for (int h = 0; h < 2; h++)
                        mma_bf16(acc[mf][np * 2 + h], ahi[mf], &bhi[h * 2]);
#pragma unroll
                for (int mf = 0; mf < 4; mf++)
#pragma unroll
                    for (int h = 0; h < 2; h++)
                        mma_bf16(acc[mf][np * 2 + h], ahi[mf], &blo[h * 2]);
#pragma unroll
                for (int mf = 0; mf < 4; mf++)
#pragma unroll
                    for (int h = 0; h < 2; h++)
                        mma_bf16(acc[mf][np * 2 + h], alo[mf], &bhi[h * 2]);
            }
        }
        __syncthreads();
    }
    // (trailing sync above guarantees smem is free for epilogue staging)

    // ---- epilogue ----
    if (OUT_MODE == 0) {
#pragma unroll
        for (int mf = 0; mf < 4; mf++) {
            const int row0 = m0 + warp_m * 64 + mf * 16 + (lane >> 2);
#pragma unroll
            for (int half = 0; half < 2; half++) {
                const int m = row0 + half * 8;
                const float bb = bias ? bias[m] : 0.0f;
                float* dst = Cf + (long)b * sC + (long)m * ldc + n0 + warp_n * 32 + (lane & 3) * 2;
#pragma unroll
                for (int nf = 0; nf < 4; nf++) {
                    float2 v;
                    v.x = acc[mf][nf][half * 2 + 0] + bb;
                    v.y = acc[mf][nf][half * 2 + 1] + bb;
                    *(float2*)(dst + nf * 8) = v;
                }
            }
        }
    } else {
        // Stage packed bf16x2 through smem; then coalesced 16B stores.
        // Row stride 68 words (272 B): bank (4r+c) all-distinct on writes,
        // 16B alignment preserved for the uint4 copy phase.
        uint32_t* s_hi = (uint32_t*)sm;
        uint32_t* s_lo = s_hi + 128 * 68;
        const bool do_exp = (OUT_MODE == 2) && (m0 < 256);
#pragma unroll
        for (int mf = 0; mf < 4; mf++) {
#pragma unroll
            for (int half = 0; half < 2; half++) {
                const int r = warp_m * 64 + mf * 16 + (lane >> 2) + half * 8;
#pragma unroll
                for (int nf = 0; nf < 4; nf++) {
                    float v0 = acc[mf][nf][half * 2 + 0];
                    float v1 = acc[mf][nf][half * 2 + 1];
                    if (do_exp) { v0 = __expf(v0); v1 = __expf(v1); }
                    __nv_bfloat16 h0, l0, h1, l1;
                    split_bf16(v0, h0, l0);
                    split_bf16(v1, h1, l1);
                    const int cw = warp_n * 16 + nf * 4 + (lane & 3);
                    s_hi[r * 68 + cw] =
                        ((uint32_t)__bfloat16_as_ushort(h1) << 16) | __bfloat16_as_ushort(h0);
                    s_lo[r * 68 + cw] =
                        ((uint32_t)__bfloat16_as_ushort(l1) << 16) | __bfloat16_as_ushort(l0);
                }
            }
        }
        __syncthreads();
        for (int i = tid; i < 128 * 16; i += 256) {
            const int r = i >> 4, seg = i & 15;
            uint4 vh = *(uint4*)&s_hi[r * 68 + seg * 4];
            uint4 vl = *(uint4*)&s_lo[r * 68 + seg * 4];
            long off = (long)b * sC + (long)(m0 + r) * ldc + n0 + seg * 8;
            *(uint4*)(Chi + off) = vh;
            *(uint4*)(Clo + off) = vl;
        }
    }
}

// ------------------------- ctx via mma --------------------------------------
// Per (b,h): C[32x48] = expK(32x4096) @ Bpad^T where Bpad rows 0-31 = V,
// row 32 = ones (-> row sums S), rows 33-47 = zero. 3-pass bf16 split.
#define CBK 128
#define CLDS 136
#define CA_ELE (32 * CLDS)
#define CB_ELE (48 * CLDS)
#define CSTAGE_ELE (2 * CA_ELE + 2 * CB_ELE)
#define CSMEM_BYTES (2 * CSTAGE_ELE * 2)

__global__ void __launch_bounds__(256) ctx_mma() {
    extern __shared__ __align__(16) __nv_bfloat16 csm[];
    const int h = blockIdx.x, b = blockIdx.y;
    const int tid = threadIdx.x, wid = tid >> 5, lane = tid & 31;

    const __nv_bfloat16* srcs[4] = {
        g_ekv_hi + ((long)b * 512 + h * 32) * NPIX,
        g_ekv_lo + ((long)b * 512 + h * 32) * NPIX,
        g_ekv_hi + ((long)b * 512 + 256 + h * 32) * NPIX,
        g_ekv_lo + ((long)b * 512 + 256 + h * 32) * NPIX};
    const uint32_t offs[4] = {0, CA_ELE, 2 * CA_ELE, 2 * CA_ELE + CB_ELE};

    const uint32_t smb = smem_u32(csm);

    const __nv_bfloat16 one = __float2bfloat16(1.0f);
    const __nv_bfloat16 zero = __float2bfloat16(0.0f);
    for (int s = 0; s < 2; s++) {
        __nv_bfloat16* Bh = csm + s * CSTAGE_ELE + 2 * CA_ELE + 32 * CLDS;
        __nv_bfloat16* Bl = csm + s * CSTAGE_ELE + 2 * CA_ELE + CB_ELE + 32 * CLDS;
        for (int i = tid; i < 16 * CLDS; i += 256) {
            Bh[i] = (i < CLDS) ? one : zero;
            Bl[i] = zero;
        }
    }

    const int lrow = tid >> 3;
    const int lseg = (tid & 7) * 16;

    auto prefetch = [&](int kc, int stage) {
        const int k0 = kc * CBK;
        const uint32_t sbase = smb + (uint32_t)stage * CSTAGE_ELE * 2;
#pragma unroll
        for (int t4 = 0; t4 < 4; t4++) {
            const __nv_bfloat16* s = srcs[t4] + (long)lrow * NPIX + k0 + lseg;
            const uint32_t d = sbase + (uint32_t)(offs[t4] + lrow * CLDS + lseg) * 2;
            cp_async16(d, s);
            cp_async16(d + 16, s + 8);
        }
        cp_commit();
    };

    float acc[2][6][4];
#pragma unroll
    for (int i = 0; i < 2; i++)
#pragma unroll
        for (int j = 0; j < 6; j++)
#pragma unroll
            for (int k = 0; k < 4; k++) acc[i][j][k] = 0.0f;

    prefetch(0, 0);

    const int kk = wid * 16;
    for (int kc = 0; kc < NPIX / CBK; kc++) {
        cp_wait<0>();
        __syncthreads();
        if (kc + 1 < NPIX / CBK) prefetch(kc + 1, (kc + 1) & 1);

        const uint32_t sbase = smb + (uint32_t)(kc & 1) * CSTAGE_ELE * 2;
        uint32_t ahi[2][4], alo[2][4];
#pragma unroll
        for (int mf = 0; mf < 2; mf++) {
            const int am = mf * 16 + (lane & 15);
            const uint32_t off = (uint32_t)(am * CLDS + kk + (lane >> 4) * 8) * 2;
            ldsm_x4(ahi[mf], sbase + off);
            ldsm_x4(alo[mf], sbase + CA_ELE * 2 + off);
        }
#pragma unroll
        for (int np = 0; np < 3; np++) {
            uint32_t bhi[4], blo[4];
            const int bn = np * 16 + ((lane & 16) >> 1) + (lane & 7);
            const uint32_t off = (uint32_t)(bn * CLDS + kk + (lane & 8)) * 2;
            ldsm_x4(bhi, sbase + 2 * CA_ELE * 2 + off);
            ldsm_x4(blo, sbase + (2 * CA_ELE + CB_ELE) * 2 + off);
#pragma unroll
            for (int mf = 0; mf < 2; mf++)
#pragma unroll
                for (int hh = 0; hh < 2; hh++) {
                    float* a = acc[mf][np * 2 + hh];
                    mma_bf16(a, ahi[mf], &bhi[hh * 2]);
                    mma_bf16(a, ahi[mf], &blo[hh * 2]);
                    mma_bf16(a, alo[mf], &bhi[hh * 2]);
                }
        }
        __syncthreads();
    }

    // ---- cross-warp reduction (reuse smem as fp32 [8][32][48]) ----
    float* red = (float*)csm;
#pragma unroll
    for (int mf = 0; mf < 2; mf++)
#pragma unroll
        for (int nf = 0; nf < 6; nf++)
#pragma unroll
            for (int i = 0; i < 4; i++) {
                int row = mf * 16 + (lane >> 2) + (i >> 1) * 8;
                int col = nf * 8 + (lane & 3) * 2 + (i & 1);
                red[((long)wid * 32 + row) * 48 + col] = acc[mf][nf][i];
            }
    __syncthreads();

    float* Cp = g_C + ((long)(b * 8 + h)) * 32 * 33;
    for (int o = tid; o < 32 * 48; o += 256) {
        int row = o / 48, col = o % 48;
        float s = 0.0f;
#pragma unroll
        for (int w = 0; w < 8; w++) s += red[((long)w * 32 + row) * 48 + col];
        if (col < 33) Cp[row * 33 + col] = s;
    }
}

// U = w_out @ blockdiag((C/S)^T), write bf16 hi/lo
__global__ void __launch_bounds__(256) u_kernel(const float* __restrict__ w_out) {
    const int h = blockIdx.x, b = blockIdx.y;
    __shared__ float Cs[32][33];
    __shared__ float s_inv[32];
    const int tid = threadIdx.x;
    const float* Cp = g_C + ((long)(b * 8 + h)) * 32 * 33;

    if (tid < 32) s_inv[tid] = 1.0f / Cp[tid * 33 + 32];
    for (int t = tid; t < 32 * 33; t += 256) Cs[t / 33][t % 33] = Cp[t];
    __syncthreads();

    const int o = tid;
    float wrow[32];
#pragma unroll
    for (int j = 0; j < 32; j += 4)
        *(float4*)&wrow[j] = *(const float4*)&w_out[(long)o * 256 + h * 32 + j];
    float acc[32];
#pragma unroll
    for (int d = 0; d < 32; d++) acc[d] = 0.0f;
#pragma unroll 8
    for (int e = 0; e < 32; e++) {
        float we = wrow[e];
#pragma unroll
        for (int d = 0; d < 32; d++) acc[d] += we * Cs[d][e];
    }
    long ub = (long)b * CD * KD + (long)o * KD + h * 32;
#pragma unroll
    for (int d = 0; d < 32; d++) {
        __nv_bfloat16 hi, lo;
        split_bf16(acc[d] * s_inv[d], hi, lo);
        g_u_hi[ub + d] = hi;
        g_u_lo[ub + d] = lo;
    }
}

// ------------------------- launch ------------------------------------------
extern "C" void kernel_launch(void* const* d_in, const int* in_sizes, int n_in,
                              void* d_out, int out_size)
{
    const float* x     = (const float*)d_in[0];
    const float* w_qkv = (const float*)d_in[1];
    const float* w_out = (const float*)d_in[2];
    const float* b_out = (const float*)d_in[3];
    float* y = (float*)d_out;

    cudaFuncSetAttribute(gemm_mma<0>, cudaFuncAttributeMaxDynamicSharedMemorySize, SMEM_BYTES);
    cudaFuncSetAttribute(gemm_mma<1>, cudaFuncAttributeMaxDynamicSharedMemorySize, SMEM_BYTES);
    cudaFuncSetAttribute(gemm_mma<2>, cudaFuncAttributeMaxDynamicSharedMemorySize, SMEM_BYTES);
    cudaFuncSetAttribute(ctx_mma, cudaFuncAttributeMaxDynamicSharedMemorySize, CSMEM_BYTES);

    __nv_bfloat16 *xt_hi, *xt_lo, *wkv_hi, *wkv_lo, *wqt_hi, *wqt_lo;
    __nv_bfloat16 *u_hi, *u_lo, *weff_hi, *weff_lo, *ekv_hi, *ekv_lo;
    cudaGetSymbolAddress((void**)&xt_hi, g_xt_hi);
    cudaGetSymbolAddress((void**)&xt_lo, g_xt_lo);
    cudaGetSymbolAddress((void**)&wkv_hi, g_wkv_hi);
    cudaGetSymbolAddress((void**)&wkv_lo, g_wkv_lo);
    cudaGetSymbolAddress((void**)&wqt_hi, g_wqt_hi);
    cudaGetSymbolAddress((void**)&wqt_lo, g_wqt_lo);
    cudaGetSymbolAddress((void**)&u_hi, g_u_hi);
    cudaGetSymbolAddress((void**)&u_lo, g_u_lo);
    cudaGetSymbolAddress((void**)&weff_hi, g_weff_hi);
    cudaGetSymbolAddress((void**)&weff_lo, g_weff_lo);
    cudaGetSymbolAddress((void**)&ekv_hi, g_ekv_hi);
    cudaGetSymbolAddress((void**)&ekv_lo, g_ekv_lo);

    // 1) conversions
    conv_x<<<dim3(NPIX / 32, NB), 256>>>(x);
    conv_wkv<<<512, 256>>>(w_qkv);
    conv_wqt<<<dim3(8, 8), 256>>>(w_qkv);

    // 2) ekv = exp/copy(wkv @ xT^T) as bf16 hi/lo (M=512, N=4096 per batch)
    gemm_mma<2><<<dim3(NPIX / 128, 4, NB), 256, SMEM_BYTES>>>(
        wkv_hi, wkv_lo, 0L, xt_hi, xt_lo, (long)NPIX * CD,
        nullptr, ekv_hi, ekv_lo, (long)512 * NPIX, NPIX, nullptr);

    // 3) C (+ row sums via ones-column) = expK @ Vpad^T, tensor-core
    ctx_mma<<<dim3(8, NB), 256, CSMEM_BYTES>>>();

    // 4) normalize + U = w_out @ blockdiag(C^T)
    u_kernel<<<dim3(8, NB), 256>>>(w_out);

    // 5) weff = U @ WqT^T   (M=256, N=256) -> bf16 hi/lo
    gemm_mma<1><<<dim3(2, 2, NB), 256, SMEM_BYTES>>>(
        u_hi, u_lo, (long)CD * KD, wqt_hi, wqt_lo, 0L,
        nullptr, weff_hi, weff_lo, (long)CD * KD, KD, nullptr);

    // 6) y = weff @ xT^T + b_out   (M=256, N=4096 per batch)
    gemm_mma<0><<<dim3(NPIX / 128, 2, NB), 256, SMEM_BYTES>>>(
        weff_hi, weff_lo, (long)CD * KD, xt_hi, xt_lo, (long)NPIX * CD,
        y, nullptr, nullptr, (long)CD * NPIX, NPIX, b_out);
}

// round 13
// speedup vs baseline: 1.4054x; 1.0554x over previous
#include <cuda_runtime.h>
#include <cuda_fp16.h>
#include <cstdint>

// ===========================================================================
// LinearAttention via mma.sync fp16 split-precision.
// R13: bf16 -> fp16 splits (11-bit hi). kv/ctx keep 3-pass (pre-exp accuracy);
//      y and weff GEMMs drop to 2-pass (full-A x B_hi), skipping B_lo loads.
// ===========================================================================

#define NB   16
#define NPIX 4096
#define CD   256
#define KD   256

__device__ __half g_xt_hi[(long)NB * NPIX * CD];
__device__ __half g_xt_lo[(long)NB * NPIX * CD];
__device__ __half g_wkv_hi[512 * KD];
__device__ __half g_wkv_lo[512 * KD];
__device__ __half g_wqt_hi[CD * KD];
__device__ __half g_wqt_lo[CD * KD];
__device__ __half g_ekv_hi[(long)NB * 512 * NPIX];  // exp(K) rows 0-255, V rows 256-511
__device__ __half g_ekv_lo[(long)NB * 512 * NPIX];
__device__ float g_C[NB * 8 * 32 * 33];             // C[32x32] + S col at 32
__device__ __half g_u_hi[NB * CD * KD];
__device__ __half g_u_lo[NB * CD * KD];
__device__ __half g_weff_hi[NB * CD * KD];
__device__ __half g_weff_lo[NB * CD * KD];

// ------------------------- helpers ----------------------------------------
__device__ __forceinline__ uint32_t smem_u32(const void* p) {
    uint32_t a;
    asm("{ .reg .u64 t; cvta.to.shared.u64 t, %1; cvt.u32.u64 %0, t; }"
        : "=r"(a) : "l"(p));
    return a;
}
__device__ __forceinline__ void ldsm_x4(uint32_t* r, uint32_t addr) {
    asm volatile("ldmatrix.sync.aligned.m8n8.x4.shared.b16 {%0,%1,%2,%3}, [%4];"
                 : "=r"(r[0]), "=r"(r[1]), "=r"(r[2]), "=r"(r[3]) : "r"(addr));
}
__device__ __forceinline__ void mma_f16(float* d, const uint32_t* a, const uint32_t* b) {
    asm volatile(
        "mma.sync.aligned.m16n8k16.row.col.f32.f16.f16.f32 "
        "{%0,%1,%2,%3}, {%4,%5,%6,%7}, {%8,%9}, {%0,%1,%2,%3};"
        : "+f"(d[0]), "+f"(d[1]), "+f"(d[2]), "+f"(d[3])
        : "r"(a[0]), "r"(a[1]), "r"(a[2]), "r"(a[3]), "r"(b[0]), "r"(b[1]));
}
__device__ __forceinline__ void cp_async16(uint32_t smem_dst, const void* gsrc) {
    asm volatile("cp.async.ca.shared.global [%0], [%1], 16;"
                 :: "r"(smem_dst), "l"(gsrc) : "memory");
}
__device__ __forceinline__ void cp_commit() {
    asm volatile("cp.async.commit_group;" ::: "memory");
}
template <int N>
__device__ __forceinline__ void cp_wait() {
    asm volatile("cp.async.wait_group %0;" :: "n"(N) : "memory");
}
__device__ __forceinline__ void split_h(float v, __half& hi, __half& lo) {
    hi = __float2half(v);
    lo = __float2half(v - __half2float(hi));
}

// ------------------------- conversion kernels ------------------------------
__global__ void __launch_bounds__(256) conv_x(const float* __restrict__ x) {
    __shared__ float sb[32][257];
    const int b = blockIdx.y, n0 = blockIdx.x * 32;
    const float* xb = x + (long)b * CD * NPIX;
    const int tn = threadIdx.x & 31, tc = threadIdx.x >> 5;

#pragma unroll
    for (int c0 = 0; c0 < 256; c0 += 8) {
        sb[tn][c0 + tc] = xb[(long)(c0 + tc) * NPIX + n0 + tn];
    }
    __syncthreads();

    const long base = (long)b * NPIX * CD;
    const int c = threadIdx.x;
#pragma unroll 4
    for (int i = 0; i < 32; i++) {
        float v = sb[i][c];
        __half hi, lo;
        split_h(v, hi, lo);
        long idx = base + (long)(n0 + i) * CD + c;
        g_xt_hi[idx] = hi;
        g_xt_lo[idx] = lo;
    }
}

__global__ void __launch_bounds__(256) conv_wkv(const float* __restrict__ w_qkv) {
    int i = blockIdx.x * 256 + threadIdx.x;
    float v = w_qkv[256 * 256 + i];
    __half hi, lo;
    split_h(v, hi, lo);
    g_wkv_hi[i] = hi;
    g_wkv_lo[i] = lo;
}

__global__ void __launch_bounds__(256) conv_wqt(const float* __restrict__ w_qkv) {
    __shared__ float t[32][33];
    const int t0 = blockIdx.x * 32, c0 = blockIdx.y * 32;
    const int tn = threadIdx.x & 31, tr = threadIdx.x >> 5;
#pragma unroll
    for (int i = 0; i < 32; i += 8)
        t[tr + i][tn] = w_qkv[(long)(t0 + tr + i) * 256 + c0 + tn];
    __syncthreads();
#pragma unroll
    for (int i = 0; i < 32; i += 8) {
        float v = t[tn][tr + i];
        __half hi, lo;
        split_h(v, hi, lo);
        long idx = (long)(c0 + tr + i) * KD + t0 + tn;
        g_wqt_hi[idx] = hi;
        g_wqt_lo[idx] = lo;
    }
}

// ------------------------- warp-MMA GEMM (cp.async 2-stage) ----------------
// Block tile 128x128, BK=32, 8 warps of 64x32.
// OUT_MODE 0: fp32+bias, 2-pass. 1: fp16 hi/lo out, 2-pass.
//          2: fp16 hi/lo out + exp() on K tiles, 3-pass.
#define BK   32
#define LDS  40
#define TILE_ELE (128 * LDS)
#define STAGE_ELE (4 * TILE_ELE)
#define SMEM_BYTES (2 * STAGE_ELE * 2)

template <int OUT_MODE>
__global__ void __launch_bounds__(256, 2) gemm_mma(
    const __half* __restrict__ Ahi, const __half* __restrict__ Alo, long sA,
    const __half* __restrict__ Bhi, const __half* __restrict__ Blo, long sB,
    float* __restrict__ Cf, __half* __restrict__ Chi, __half* __restrict__ Clo,
    long sC, int ldc, const float* __restrict__ bias)
{
    extern __shared__ __align__(16) __half sm[];
    constexpr bool THREE_PASS = (OUT_MODE == 2);
    constexpr int NTILES = THREE_PASS ? 4 : 3;

    const int tid = threadIdx.x, wid = tid >> 5, lane = tid & 31;
    const int warp_m = wid >> 2, warp_n = wid & 3;
    const int b = blockIdx.z;
    const int m0 = blockIdx.y * 128, n0 = blockIdx.x * 128;

    const __half* srcs[4] = {
        Ahi + (long)b * sA + (long)m0 * KD,
        Alo + (long)b * sA + (long)m0 * KD,
        Bhi + (long)b * sB + (long)n0 * KD,
        THREE_PASS ? (Blo + (long)b * sB + (long)n0 * KD) : nullptr};

    const uint32_t smb = smem_u32(sm);

    const int ldrow = tid >> 1;
    const int ldseg = (tid & 1) * 8;

    auto prefetch = [&](int kc, int stage) {
        const int k0 = kc * BK;
        const uint32_t sbase = smb + (uint32_t)stage * STAGE_ELE * 2;
#pragma unroll
        for (int t4 = 0; t4 < NTILES; t4++) {
            const __half* s = srcs[t4] + (long)ldrow * KD + k0 + ldseg;
            const uint32_t d = sbase + (uint32_t)(t4 * TILE_ELE + ldrow * LDS + ldseg) * 2;
            cp_async16(d, s);
            cp_async16(d + 32, s + 16);
        }
        cp_commit();
    };

    float acc[4][4][4];
#pragma unroll
    for (int i = 0; i < 4; i++)
#pragma unroll
        for (int j = 0; j < 4; j++)
#pragma unroll
            for (int k = 0; k < 4; k++) acc[i][j][k] = 0.0f;

    prefetch(0, 0);

    for (int kc = 0; kc < 8; kc++) {
        cp_wait<0>();
        __syncthreads();
        if (kc + 1 < 8) prefetch(kc + 1, (kc + 1) & 1);

        const uint32_t sbase = smb + (uint32_t)(kc & 1) * STAGE_ELE * 2;
#pragma unroll
        for (int ks = 0; ks < 2; ks++) {
            const int kk = ks * 16;
            uint32_t ahi[4][4], alo[4][4];
#pragma unroll
            for (int mf = 0; mf < 4; mf++) {
                const int am = warp_m * 64 + mf * 16 + (lane & 15);
                const uint32_t off = (uint32_t)(am * LDS + kk + (lane >> 4) * 8) * 2;
                ldsm_x4(ahi[mf], sbase + (0 * TILE_ELE) * 2 + off);
                ldsm_x4(alo[mf], sbase + (1 * TILE_ELE) * 2 + off);
            }
#pragma unroll
            for (int np = 0; np < 2; np++) {
                uint32_t bhi[4], blo[4];
                const int bn = warp_n * 32 + np * 16 + ((lane & 16) >> 1) + (lane & 7);
                const uint32_t off = (uint32_t)(bn * LDS + kk + (lane & 8)) * 2;
                ldsm_x4(bhi, sbase + (2 * TILE_ELE) * 2 + off);
                if (THREE_PASS)
                    ldsm_x4(blo, sbase + (3 * TILE_ELE) * 2 + off);
                // Pass 1: Ahi x Bhi
#pragma unroll
                for (int mf = 0; mf < 4; mf++)
#pragma unroll
                    for (int h = 0; h < 2; h++)
                        mma_f16(acc[mf][np * 2 + h], ahi[mf], &bhi[h * 2]);
                // Pass 2: Alo x Bhi (full-A precision)
#pragma unroll
                for (int mf = 0; mf < 4; mf++)
#pragma unroll
                    for (int h = 0; h < 2; h++)
                        mma_f16(acc[mf][np * 2 + h], alo[mf], &bhi[h * 2]);
                // Pass 3 (kv only): Ahi x Blo
                if (THREE_PASS) {
#pragma unroll
                    for (int mf = 0; mf < 4; mf++)
#pragma unroll
                        for (int h = 0; h < 2; h++)
                            mma_f16(acc[mf][np * 2 + h], ahi[mf], &blo[h * 2]);
                }
            }
        }
        __syncthreads();
    }

    // ---- epilogue ----
    if (OUT_MODE == 0) {
#pragma unroll
        for (int mf = 0; mf < 4; mf++) {
            const int row0 = m0 + warp_m * 64 + mf * 16 + (lane >> 2);
#pragma unroll
            for (int half_i = 0; half_i < 2; half_i++) {
                const int m = row0 + half_i * 8;
                const float bb = bias ? bias[m] : 0.0f;
                float* dst = Cf + (long)b * sC + (long)m * ldc + n0 + warp_n * 32 + (lane & 3) * 2;
#pragma unroll
                for (int nf = 0; nf < 4; nf++) {
                    float2 v;
                    v.x = acc[mf][nf][half_i * 2 + 0] + bb;
                    v.y = acc[mf][nf][half_i * 2 + 1] + bb;
                    *(float2*)(dst + nf * 8) = v;
                }
            }
        }
    } else {
        // Stage packed half2 through smem; then coalesced 16B stores.
        uint32_t* s_hi = (uint32_t*)sm;
        uint32_t* s_lo = s_hi + 128 * 68;
        const bool do_exp = (OUT_MODE == 2) && (m0 < 256);
#pragma unroll
        for (int mf = 0; mf < 4; mf++) {
#pragma unroll
            for (int half_i = 0; half_i < 2; half_i++) {
                const int r = warp_m * 64 + mf * 16 + (lane >> 2) + half_i * 8;
#pragma unroll
                for (int nf = 0; nf < 4; nf++) {
                    float v0 = acc[mf][nf][half_i * 2 + 0];
                    float v1 = acc[mf][nf][half_i * 2 + 1];
                    if (do_exp) { v0 = __expf(v0); v1 = __expf(v1); }
                    __half h0, l0, h1, l1;
                    split_h(v0, h0, l0);
                    split_h(v1, h1, l1);
                    const int cw = warp_n * 16 + nf * 4 + (lane & 3);
                    s_hi[r * 68 + cw] =
                        ((uint32_t)__half_as_ushort(h1) << 16) | __half_as_ushort(h0);
                    s_lo[r * 68 + cw] =
                        ((uint32_t)__half_as_ushort(l1) << 16) | __half_as_ushort(l0);
                }
            }
        }
        __syncthreads();
        for (int i = tid; i < 128 * 16; i += 256) {
            const int r = i >> 4, seg = i & 15;
            uint4 vh = *(uint4*)&s_hi[r * 68 + seg * 4];
            uint4 vl = *(uint4*)&s_lo[r * 68 + seg * 4];
            long off = (long)b * sC + (long)(m0 + r) * ldc + n0 + seg * 8;
            *(uint4*)(Chi + off) = vh;
            *(uint4*)(Clo + off) = vl;
        }
    }
}

// ------------------------- ctx via mma --------------------------------------
// Per (b,h): C[32x48] = expK(32x4096) @ Bpad^T, row 32 of Bpad = ones -> sums.
#define CBK 128
#define CLDS 136
#define CA_ELE (32 * CLDS)
#define CB_ELE (48 * CLDS)
#define CSTAGE_ELE (2 * CA_ELE + 2 * CB_ELE)
#define CSMEM_BYTES (2 * CSTAGE_ELE * 2)

__global__ void __launch_bounds__(256) ctx_mma() {
    extern __shared__ __align__(16) __half csm[];
    const int h = blockIdx.x, b = blockIdx.y;
    const int tid = threadIdx.x, wid = tid >> 5, lane = tid & 31;

    const __half* srcs[4] = {
        g_ekv_hi + ((long)b * 512 + h * 32) * NPIX,
        g_ekv_lo + ((long)b * 512 + h * 32) * NPIX,
        g_ekv_hi + ((long)b * 512 + 256 + h * 32) * NPIX,
        g_ekv_lo + ((long)b * 512 + 256 + h * 32) * NPIX};
    const uint32_t offs[4] = {0, CA_ELE, 2 * CA_ELE, 2 * CA_ELE + CB_ELE};

    const uint32_t smb = smem_u32(csm);

    const __half one = __float2half(1.0f);
    const __half zero = __float2half(0.0f);
    for (int s = 0; s < 2; s++) {
        __half* Bh = csm + s * CSTAGE_ELE + 2 * CA_ELE + 32 * CLDS;
        __half* Bl = csm + s * CSTAGE_ELE + 2 * CA_ELE + CB_ELE + 32 * CLDS;
        for (int i = tid; i < 16 * CLDS; i += 256) {
            Bh[i] = (i < CLDS) ? one : zero;
            Bl[i] = zero;
        }
    }

    const int lrow = tid >> 3;
    const int lseg = (tid & 7) * 16;

    auto prefetch = [&](int kc, int stage) {
        const int k0 = kc * CBK;
        const uint32_t sbase = smb + (uint32_t)stage * CSTAGE_ELE * 2;
#pragma unroll
        for (int t4 = 0; t4 < 4; t4++) {
            const __half* s = srcs[t4] + (long)lrow * NPIX + k0 + lseg;
            const uint32_t d = sbase + (uint32_t)(offs[t4] + lrow * CLDS + lseg) * 2;
            cp_async16(d, s);
            cp_async16(d + 16, s + 8);
        }
        cp_commit();
    };

    float acc[2][6][4];
#pragma unroll
    for (int i = 0; i < 2; i++)
#pragma unroll
        for (int j = 0; j < 6; j++)
#pragma unroll
            for (int k = 0; k < 4; k++) acc[i][j][k] = 0.0f;

    prefetch(0, 0);

    const int kk = wid * 16;
    for (int kc = 0; kc < NPIX / CBK; kc++) {
        cp_wait<0>();
        __syncthreads();
        if (kc + 1 < NPIX / CBK) prefetch(kc + 1, (kc + 1) & 1);

        const uint32_t sbase = smb + (uint32_t)(kc & 1) * CSTAGE_ELE * 2;
        uint32_t ahi[2][4], alo[2][4];
#pragma unroll
        for (int mf = 0; mf < 2; mf++) {
            const int am = mf * 16 + (lane & 15);
            const uint32_t off = (uint32_t)(am * CLDS + kk + (lane >> 4) * 8) * 2;
            ldsm_x4(ahi[mf], sbase + off);
            ldsm_x4(alo[mf], sbase + CA_ELE * 2 + off);
        }
#pragma unroll
        for (int np = 0; np < 3; np++) {
            uint32_t bhi[4], blo[4];
            const int bn = np * 16 + ((lane & 16) >> 1) + (lane & 7);
            const uint32_t off = (uint32_t)(bn * CLDS + kk + (lane & 8)) * 2;
            ldsm_x4(bhi, sbase + 2 * CA_ELE * 2 + off);
            ldsm_x4(blo, sbase + (2 * CA_ELE + CB_ELE) * 2 + off);
#pragma unroll
            for (int mf = 0; mf < 2; mf++)
#pragma unroll
                for (int hh = 0; hh < 2; hh++) {
                    float* a = acc[mf][np * 2 + hh];
                    mma_f16(a, ahi[mf], &bhi[hh * 2]);
                    mma_f16(a, ahi[mf], &blo[hh * 2]);
                    mma_f16(a, alo[mf], &bhi[hh * 2]);
                }
        }
        __syncthreads();
    }

    // ---- cross-warp reduction (reuse smem as fp32 [8][32][48]) ----
    float* red = (float*)csm;
#pragma unroll
    for (int mf = 0; mf < 2; mf++)
#pragma unroll
        for (int nf = 0; nf < 6; nf++)
#pragma unroll
            for (int i = 0; i < 4; i++) {
                int row = mf * 16 + (lane >> 2) + (i >> 1) * 8;
                int col = nf * 8 + (lane & 3) * 2 + (i & 1);
                red[((long)wid * 32 + row) * 48 + col] = acc[mf][nf][i];
            }
    __syncthreads();

    float* Cp = g_C + ((long)(b * 8 + h)) * 32 * 33;
    for (int o = tid; o < 32 * 48; o += 256) {
        int row = o / 48, col = o % 48;
        float s = 0.0f;
#pragma unroll
        for (int w = 0; w < 8; w++) s += red[((long)w * 32 + row) * 48 + col];
        if (col < 33) Cp[row * 33 + col] = s;
    }
}

// U = w_out @ blockdiag((C/S)^T), write fp16 hi/lo
__global__ void __launch_bounds__(256) u_kernel(const float* __restrict__ w_out) {
    const int h = blockIdx.x, b = blockIdx.y;
    __shared__ float Cs[32][33];
    __shared__ float s_inv[32];
    const int tid = threadIdx.x;
    const float* Cp = g_C + ((long)(b * 8 + h)) * 32 * 33;

    if (tid < 32) s_inv[tid] = 1.0f / Cp[tid * 33 + 32];
    for (int t = tid; t < 32 * 33; t += 256) Cs[t / 33][t % 33] = Cp[t];
    __syncthreads();

    const int o = tid;
    float wrow[32];
#pragma unroll
    for (int j = 0; j < 32; j += 4)
        *(float4*)&wrow[j] = *(const float4*)&w_out[(long)o * 256 + h * 32 + j];
    float acc[32];
#pragma unroll
    for (int d = 0; d < 32; d++) acc[d] = 0.0f;
#pragma unroll 8
    for (int e = 0; e < 32; e++) {
        float we = wrow[e];
#pragma unroll
        for (int d = 0; d < 32; d++) acc[d] += we * Cs[d][e];
    }
    long ub = (long)b * CD * KD + (long)o * KD + h * 32;
#pragma unroll
    for (int d = 0; d < 32; d++) {
        __half hi, lo;
        split_h(acc[d] * s_inv[d], hi, lo);
        g_u_hi[ub + d] = hi;
        g_u_lo[ub + d] = lo;
    }
}

// ------------------------- launch ------------------------------------------
extern "C" void kernel_launch(void* const* d_in, const int* in_sizes, int n_in,
                              void* d_out, int out_size)
{
    const float* x     = (const float*)d_in[0];
    const float* w_qkv = (const float*)d_in[1];
    const float* w_out = (const float*)d_in[2];
    const float* b_out = (const float*)d_in[3];
    float* y = (float*)d_out;

    cudaFuncSetAttribute(gemm_mma<0>, cudaFuncAttributeMaxDynamicSharedMemorySize, SMEM_BYTES);
    cudaFuncSetAttribute(gemm_mma<1>, cudaFuncAttributeMaxDynamicSharedMemorySize, SMEM_BYTES);
    cudaFuncSetAttribute(gemm_mma<2>, cudaFuncAttributeMaxDynamicSharedMemorySize, SMEM_BYTES);
    cudaFuncSetAttribute(ctx_mma, cudaFuncAttributeMaxDynamicSharedMemorySize, CSMEM_BYTES);

    __half *xt_hi, *xt_lo, *wkv_hi, *wkv_lo, *wqt_hi, *wqt_lo;
    __half *u_hi, *u_lo, *weff_hi, *weff_lo, *ekv_hi, *ekv_lo;
    cudaGetSymbolAddress((void**)&xt_hi, g_xt_hi);
    cudaGetSymbolAddress((void**)&xt_lo, g_xt_lo);
    cudaGetSymbolAddress((void**)&wkv_hi, g_wkv_hi);
    cudaGetSymbolAddress((void**)&wkv_lo, g_wkv_lo);
    cudaGetSymbolAddress((void**)&wqt_hi, g_wqt_hi);
    cudaGetSymbolAddress((void**)&wqt_lo, g_wqt_lo);
    cudaGetSymbolAddress((void**)&u_hi, g_u_hi);
    cudaGetSymbolAddress((void**)&u_lo, g_u_lo);
    cudaGetSymbolAddress((void**)&weff_hi, g_weff_hi);
    cudaGetSymbolAddress((void**)&weff_lo, g_weff_lo);
    cudaGetSymbolAddress((void**)&ekv_hi, g_ekv_hi);
    cudaGetSymbolAddress((void**)&ekv_lo, g_ekv_lo);

    // 1) conversions
    conv_x<<<dim3(NPIX / 32, NB), 256>>>(x);
    conv_wkv<<<512, 256>>>(w_qkv);
    conv_wqt<<<dim3(8, 8), 256>>>(w_qkv);

    // 2) ekv = exp/copy(wkv @ xT^T), 3-pass fp16 (M=512, N=4096 per batch)
    gemm_mma<2><<<dim3(NPIX / 128, 4, NB), 256, SMEM_BYTES>>>(
        wkv_hi, wkv_lo, 0L, xt_hi, xt_lo, (long)NPIX * CD,
        nullptr, ekv_hi, ekv_lo, (long)512 * NPIX, NPIX, nullptr);

    // 3) C (+ row sums) = expK @ Vpad^T, tensor-core, 3-pass
    ctx_mma<<<dim3(8, NB), 256, CSMEM_BYTES>>>();

    // 4) normalize + U = w_out @ blockdiag(C^T)
    u_kernel<<<dim3(8, NB), 256>>>(w_out);

    // 5) weff = U @ WqT^T, 2-pass (M=256, N=256) -> fp16 hi/lo
    gemm_mma<1><<<dim3(2, 2, NB), 256, SMEM_BYTES>>>(
        u_hi, u_lo, (long)CD * KD, wqt_hi, nullptr, 0L,
        nullptr, weff_hi, weff_lo, (long)CD * KD, KD, nullptr);

    // 6) y = weff @ xT^T + b_out, 2-pass (M=256, N=4096 per batch)
    gemm_mma<0><<<dim3(NPIX / 128, 2, NB), 256, SMEM_BYTES>>>(
        weff_hi, weff_lo, (long)CD * KD, xt_hi, nullptr, (long)NPIX * CD,
        y, nullptr, nullptr, (long)CD * NPIX, NPIX, b_out);
}

// round 14
// speedup vs baseline: 1.4575x; 1.0371x over previous
#include <cuda_runtime.h>
#include <cuda_fp16.h>
#include <cstdint>

// ===========================================================================
// LinearAttention via mma.sync fp16 split-precision.
// R14 = R13 + kv launch split: K half (rows 0-255) stays 3-pass + exp;
//       V half (rows 256-511) drops to 2-pass via the proven mode-1 path
//       (x_lo never loaded). Only launch-level change.
// ===========================================================================

#define NB   16
#define NPIX 4096
#define CD   256
#define KD   256

__device__ __half g_xt_hi[(long)NB * NPIX * CD];
__device__ __half g_xt_lo[(long)NB * NPIX * CD];
__device__ __half g_wkv_hi[512 * KD];
__device__ __half g_wkv_lo[512 * KD];
__device__ __half g_wqt_hi[CD * KD];
__device__ __half g_wqt_lo[CD * KD];
__device__ __half g_ekv_hi[(long)NB * 512 * NPIX];  // exp(K) rows 0-255, V rows 256-511
__device__ __half g_ekv_lo[(long)NB * 512 * NPIX];
__device__ float g_C[NB * 8 * 32 * 33];             // C[32x32] + S col at 32
__device__ __half g_u_hi[NB * CD * KD];
__device__ __half g_u_lo[NB * CD * KD];
__device__ __half g_weff_hi[NB * CD * KD];
__device__ __half g_weff_lo[NB * CD * KD];

// ------------------------- helpers ----------------------------------------
__device__ __forceinline__ uint32_t smem_u32(const void* p) {
    uint32_t a;
    asm("{ .reg .u64 t; cvta.to.shared.u64 t, %1; cvt.u32.u64 %0, t; }"
        : "=r"(a) : "l"(p));
    return a;
}
__device__ __forceinline__ void ldsm_x4(uint32_t* r, uint32_t addr) {
    asm volatile("ldmatrix.sync.aligned.m8n8.x4.shared.b16 {%0,%1,%2,%3}, [%4];"
                 : "=r"(r[0]), "=r"(r[1]), "=r"(r[2]), "=r"(r[3]) : "r"(addr));
}
__device__ __forceinline__ void mma_f16(float* d, const uint32_t* a, const uint32_t* b) {
    asm volatile(
        "mma.sync.aligned.m16n8k16.row.col.f32.f16.f16.f32 "
        "{%0,%1,%2,%3}, {%4,%5,%6,%7}, {%8,%9}, {%0,%1,%2,%3};"
        : "+f"(d[0]), "+f"(d[1]), "+f"(d[2]), "+f"(d[3])
        : "r"(a[0]), "r"(a[1]), "r"(a[2]), "r"(a[3]), "r"(b[0]), "r"(b[1]));
}
__device__ __forceinline__ void cp_async16(uint32_t smem_dst, const void* gsrc) {
    asm volatile("cp.async.ca.shared.global [%0], [%1], 16;"
                 :: "r"(smem_dst), "l"(gsrc) : "memory");
}
__device__ __forceinline__ void cp_commit() {
    asm volatile("cp.async.commit_group;" ::: "memory");
}
template <int N>
__device__ __forceinline__ void cp_wait() {
    asm volatile("cp.async.wait_group %0;" :: "n"(N) : "memory");
}
__device__ __forceinline__ void split_h(float v, __half& hi, __half& lo) {
    hi = __float2half(v);
    lo = __float2half(v - __half2float(hi));
}

// ------------------------- conversion kernels ------------------------------
__global__ void __launch_bounds__(256) conv_x(const float* __restrict__ x) {
    __shared__ float sb[32][257];
    const int b = blockIdx.y, n0 = blockIdx.x * 32;
    const float* xb = x + (long)b * CD * NPIX;
    const int tn = threadIdx.x & 31, tc = threadIdx.x >> 5;

#pragma unroll
    for (int c0 = 0; c0 < 256; c0 += 8) {
        sb[tn][c0 + tc] = xb[(long)(c0 + tc) * NPIX + n0 + tn];
    }
    __syncthreads();

    const long base = (long)b * NPIX * CD;
    const int c = threadIdx.x;
#pragma unroll 4
    for (int i = 0; i < 32; i++) {
        float v = sb[i][c];
        __half hi, lo;
        split_h(v, hi, lo);
        long idx = base + (long)(n0 + i) * CD + c;
        g_xt_hi[idx] = hi;
        g_xt_lo[idx] = lo;
    }
}

__global__ void __launch_bounds__(256) conv_wkv(const float* __restrict__ w_qkv) {
    int i = blockIdx.x * 256 + threadIdx.x;
    float v = w_qkv[256 * 256 + i];
    __half hi, lo;
    split_h(v, hi, lo);
    g_wkv_hi[i] = hi;
    g_wkv_lo[i] = lo;
}

__global__ void __launch_bounds__(256) conv_wqt(const float* __restrict__ w_qkv) {
    __shared__ float t[32][33];
    const int t0 = blockIdx.x * 32, c0 = blockIdx.y * 32;
    const int tn = threadIdx.x & 31, tr = threadIdx.x >> 5;
#pragma unroll
    for (int i = 0; i < 32; i += 8)
        t[tr + i][tn] = w_qkv[(long)(t0 + tr + i) * 256 + c0 + tn];
    __syncthreads();
#pragma unroll
    for (int i = 0; i < 32; i += 8) {
        float v = t[tn][tr + i];
        __half hi, lo;
        split_h(v, hi, lo);
        long idx = (long)(c0 + tr + i) * KD + t0 + tn;
        g_wqt_hi[idx] = hi;
        g_wqt_lo[idx] = lo;
    }
}

// ------------------------- warp-MMA GEMM (cp.async 2-stage) ----------------
// Block tile 128x128, BK=32, 8 warps of 64x32.
// OUT_MODE 0: fp32+bias, 2-pass. 1: fp16 hi/lo out, 2-pass.
//          2: fp16 hi/lo out + exp(), 3-pass.
#define BK   32
#define LDS  40
#define TILE_ELE (128 * LDS)
#define STAGE_ELE (4 * TILE_ELE)
#define SMEM_BYTES (2 * STAGE_ELE * 2)

template <int OUT_MODE>
__global__ void __launch_bounds__(256, 2) gemm_mma(
    const __half* __restrict__ Ahi, const __half* __restrict__ Alo, long sA,
    const __half* __restrict__ Bhi, const __half* __restrict__ Blo, long sB,
    float* __restrict__ Cf, __half* __restrict__ Chi, __half* __restrict__ Clo,
    long sC, int ldc, const float* __restrict__ bias)
{
    extern __shared__ __align__(16) __half sm[];
    constexpr bool THREE_PASS = (OUT_MODE == 2);
    constexpr int NTILES = THREE_PASS ? 4 : 3;

    const int tid = threadIdx.x, wid = tid >> 5, lane = tid & 31;
    const int warp_m = wid >> 2, warp_n = wid & 3;
    const int b = blockIdx.z;
    const int m0 = blockIdx.y * 128, n0 = blockIdx.x * 128;

    const __half* srcs[4] = {
        Ahi + (long)b * sA + (long)m0 * KD,
        Alo + (long)b * sA + (long)m0 * KD,
        Bhi + (long)b * sB + (long)n0 * KD,
        THREE_PASS ? (Blo + (long)b * sB + (long)n0 * KD) : nullptr};

    const uint32_t smb = smem_u32(sm);

    const int ldrow = tid >> 1;
    const int ldseg = (tid & 1) * 8;

    auto prefetch = [&](int kc, int stage) {
        const int k0 = kc * BK;
        const uint32_t sbase = smb + (uint32_t)stage * STAGE_ELE * 2;
#pragma unroll
        for (int t4 = 0; t4 < NTILES; t4++) {
            const __half* s = srcs[t4] + (long)ldrow * KD + k0 + ldseg;
            const uint32_t d = sbase + (uint32_t)(t4 * TILE_ELE + ldrow * LDS + ldseg) * 2;
            cp_async16(d, s);
            cp_async16(d + 32, s + 16);
        }
        cp_commit();
    };

    float acc[4][4][4];
#pragma unroll
    for (int i = 0; i < 4; i++)
#pragma unroll
        for (int j = 0; j < 4; j++)
#pragma unroll
            for (int k = 0; k < 4; k++) acc[i][j][k] = 0.0f;

    prefetch(0, 0);

    for (int kc = 0; kc < 8; kc++) {
        cp_wait<0>();
        __syncthreads();
        if (kc + 1 < 8) prefetch(kc + 1, (kc + 1) & 1);

        const uint32_t sbase = smb + (uint32_t)(kc & 1) * STAGE_ELE * 2;
#pragma unroll
        for (int ks = 0; ks < 2; ks++) {
            const int kk = ks * 16;
            uint32_t ahi[4][4], alo[4][4];
#pragma unroll
            for (int mf = 0; mf < 4; mf++) {
                const int am = warp_m * 64 + mf * 16 + (lane & 15);
                const uint32_t off = (uint32_t)(am * LDS + kk + (lane >> 4) * 8) * 2;
                ldsm_x4(ahi[mf], sbase + (0 * TILE_ELE) * 2 + off);
                ldsm_x4(alo[mf], sbase + (1 * TILE_ELE) * 2 + off);
            }
#pragma unroll
            for (int np = 0; np < 2; np++) {
                uint32_t bhi[4], blo[4];
                const int bn = warp_n * 32 + np * 16 + ((lane & 16) >> 1) + (lane & 7);
                const uint32_t off = (uint32_t)(bn * LDS + kk + (lane & 8)) * 2;
                ldsm_x4(bhi, sbase + (2 * TILE_ELE) * 2 + off);
                if (THREE_PASS)
                    ldsm_x4(blo, sbase + (3 * TILE_ELE) * 2 + off);
                // Pass 1: Ahi x Bhi
#pragma unroll
                for (int mf = 0; mf < 4; mf++)
#pragma unroll
                    for (int h = 0; h < 2; h++)
                        mma_f16(acc[mf][np * 2 + h], ahi[mf], &bhi[h * 2]);
                // Pass 2: Alo x Bhi (full-A precision)
#pragma unroll
                for (int mf = 0; mf < 4; mf++)
#pragma unroll
                    for (int h = 0; h < 2; h++)
                        mma_f16(acc[mf][np * 2 + h], alo[mf], &bhi[h * 2]);
                // Pass 3: Ahi x Blo
                if (THREE_PASS) {
#pragma unroll
                    for (int mf = 0; mf < 4; mf++)
#pragma unroll
                        for (int h = 0; h < 2; h++)
                            mma_f16(acc[mf][np * 2 + h], ahi[mf], &blo[h * 2]);
                }
            }
        }
        __syncthreads();
    }

    // ---- epilogue ----
    if (OUT_MODE == 0) {
#pragma unroll
        for (int mf = 0; mf < 4; mf++) {
            const int row0 = m0 + warp_m * 64 + mf * 16 + (lane >> 2);
#pragma unroll
            for (int half_i = 0; half_i < 2; half_i++) {
                const int m = row0 + half_i * 8;
                const float bb = bias ? bias[m] : 0.0f;
                float* dst = Cf + (long)b * sC + (long)m * ldc + n0 + warp_n * 32 + (lane & 3) * 2;
#pragma unroll
                for (int nf = 0; nf < 4; nf++) {
                    float2 v;
                    v.x = acc[mf][nf][half_i * 2 + 0] + bb;
                    v.y = acc[mf][nf][half_i * 2 + 1] + bb;
                    *(float2*)(dst + nf * 8) = v;
                }
            }
        }
    } else {
        // Stage packed half2 through smem; then coalesced 16B stores.
        uint32_t* s_hi = (uint32_t*)sm;
        uint32_t* s_lo = s_hi + 128 * 68;
        const bool do_exp = (OUT_MODE == 2);
#pragma unroll
        for (int mf = 0; mf < 4; mf++) {
#pragma unroll
            for (int half_i = 0; half_i < 2; half_i++) {
                const int r = warp_m * 64 + mf * 16 + (lane >> 2) + half_i * 8;
#pragma unroll
                for (int nf = 0; nf < 4; nf++) {
                    float v0 = acc[mf][nf][half_i * 2 + 0];
                    float v1 = acc[mf][nf][half_i * 2 + 1];
                    if (do_exp) { v0 = __expf(v0); v1 = __expf(v1); }
                    __half h0, l0, h1, l1;
                    split_h(v0, h0, l0);
                    split_h(v1, h1, l1);
                    const int cw = warp_n * 16 + nf * 4 + (lane & 3);
                    s_hi[r * 68 + cw] =
                        ((uint32_t)__half_as_ushort(h1) << 16) | __half_as_ushort(h0);
                    s_lo[r * 68 + cw] =
                        ((uint32_t)__half_as_ushort(l1) << 16) | __half_as_ushort(l0);
                }
            }
        }
        __syncthreads();
        for (int i = tid; i < 128 * 16; i += 256) {
            const int r = i >> 4, seg = i & 15;
            uint4 vh = *(uint4*)&s_hi[r * 68 + seg * 4];
            uint4 vl = *(uint4*)&s_lo[r * 68 + seg * 4];
            long off = (long)b * sC + (long)(m0 + r) * ldc + n0 + seg * 8;
            *(uint4*)(Chi + off) = vh;
            *(uint4*)(Clo + off) = vl;
        }
    }
}

// ------------------------- ctx via mma --------------------------------------
// Per (b,h): C[32x48] = expK(32x4096) @ Bpad^T, row 32 of Bpad = ones -> sums.
#define CBK 128
#define CLDS 136
#define CA_ELE (32 * CLDS)
#define CB_ELE (48 * CLDS)
#define CSTAGE_ELE (2 * CA_ELE + 2 * CB_ELE)
#define CSMEM_BYTES (2 * CSTAGE_ELE * 2)

__global__ void __launch_bounds__(256) ctx_mma() {
    extern __shared__ __align__(16) __half csm[];
    const int h = blockIdx.x, b = blockIdx.y;
    const int tid = threadIdx.x, wid = tid >> 5, lane = tid & 31;

    const __half* srcs[4] = {
        g_ekv_hi + ((long)b * 512 + h * 32) * NPIX,
        g_ekv_lo + ((long)b * 512 + h * 32) * NPIX,
        g_ekv_hi + ((long)b * 512 + 256 + h * 32) * NPIX,
        g_ekv_lo + ((long)b * 512 + 256 + h * 32) * NPIX};
    const uint32_t offs[4] = {0, CA_ELE, 2 * CA_ELE, 2 * CA_ELE + CB_ELE};

    const uint32_t smb = smem_u32(csm);

    const __half one = __float2half(1.0f);
    const __half zero = __float2half(0.0f);
    for (int s = 0; s < 2; s++) {
        __half* Bh = csm + s * CSTAGE_ELE + 2 * CA_ELE + 32 * CLDS;
        __half* Bl = csm + s * CSTAGE_ELE + 2 * CA_ELE + CB_ELE + 32 * CLDS;
        for (int i = tid; i < 16 * CLDS; i += 256) {
            Bh[i] = (i < CLDS) ? one : zero;
            Bl[i] = zero;
        }
    }

    const int lrow = tid >> 3;
    const int lseg = (tid & 7) * 16;

    auto prefetch = [&](int kc, int stage) {
        const int k0 = kc * CBK;
        const uint32_t sbase = smb + (uint32_t)stage * CSTAGE_ELE * 2;
#pragma unroll
        for (int t4 = 0; t4 < 4; t4++) {
            const __half* s = srcs[t4] + (long)lrow * NPIX + k0 + lseg;
            const uint32_t d = sbase + (uint32_t)(offs[t4] + lrow * CLDS + lseg) * 2;
            cp_async16(d, s);
            cp_async16(d + 16, s + 8);
        }
        cp_commit();
    };

    float acc[2][6][4];
#pragma unroll
    for (int i = 0; i < 2; i++)
#pragma unroll
        for (int j = 0; j < 6; j++)
#pragma unroll
            for (int k = 0; k < 4; k++) acc[i][j][k] = 0.0f;

    prefetch(0, 0);

    const int kk = wid * 16;
    for (int kc = 0; kc < NPIX / CBK; kc++) {
        cp_wait<0>();
        __syncthreads();
        if (kc + 1 < NPIX / CBK) prefetch(kc + 1, (kc + 1) & 1);

        const uint32_t sbase = smb + (uint32_t)(kc & 1) * CSTAGE_ELE * 2;
        uint32_t ahi[2][4], alo[2][4];
#pragma unroll
        for (int mf = 0; mf < 2; mf++) {
            const int am = mf * 16 + (lane & 15);
            const uint32_t off = (uint32_t)(am * CLDS + kk + (lane >> 4) * 8) * 2;
            ldsm_x4(ahi[mf], sbase + off);
            ldsm_x4(alo[mf], sbase + CA_ELE * 2 + off);
        }
#pragma unroll
        for (int np = 0; np < 3; np++) {
            uint32_t bhi[4], blo[4];
            const int bn = np * 16 + ((lane & 16) >> 1) + (lane & 7);
            const uint32_t off = (uint32_t)(bn * CLDS + kk + (lane & 8)) * 2;
            ldsm_x4(bhi, sbase + 2 * CA_ELE * 2 + off);
            ldsm_x4(blo, sbase + (2 * CA_ELE + CB_ELE) * 2 + off);
#pragma unroll
            for (int mf = 0; mf < 2; mf++)
#pragma unroll
                for (int hh = 0; hh < 2; hh++) {
                    float* a = acc[mf][np * 2 + hh];
                    mma_f16(a, ahi[mf], &bhi[hh * 2]);
                    mma_f16(a, ahi[mf], &blo[hh * 2]);
                    mma_f16(a, alo[mf], &bhi[hh * 2]);
                }
        }
        __syncthreads();
    }

    // ---- cross-warp reduction (reuse smem as fp32 [8][32][48]) ----
    float* red = (float*)csm;
#pragma unroll
    for (int mf = 0; mf < 2; mf++)
#pragma unroll
        for (int nf = 0; nf < 6; nf++)
#pragma unroll
            for (int i = 0; i < 4; i++) {
                int row = mf * 16 + (lane >> 2) + (i >> 1) * 8;
                int col = nf * 8 + (lane & 3) * 2 + (i & 1);
                red[((long)wid * 32 + row) * 48 + col] = acc[mf][nf][i];
            }
    __syncthreads();

    float* Cp = g_C + ((long)(b * 8 + h)) * 32 * 33;
    for (int o = tid; o < 32 * 48; o += 256) {
        int row = o / 48, col = o % 48;
        float s = 0.0f;
#pragma unroll
        for (int w = 0; w < 8; w++) s += red[((long)w * 32 + row) * 48 + col];
        if (col < 33) Cp[row * 33 + col] = s;
    }
}

// U = w_out @ blockdiag((C/S)^T), write fp16 hi/lo
__global__ void __launch_bounds__(256) u_kernel(const float* __restrict__ w_out) {
    const int h = blockIdx.x, b = blockIdx.y;
    __shared__ float Cs[32][33];
    __shared__ float s_inv[32];
    const int tid = threadIdx.x;
    const float* Cp = g_C + ((long)(b * 8 + h)) * 32 * 33;

    if (tid < 32) s_inv[tid] = 1.0f / Cp[tid * 33 + 32];
    for (int t = tid; t < 32 * 33; t += 256) Cs[t / 33][t % 33] = Cp[t];
    __syncthreads();

    const int o = tid;
    float wrow[32];
#pragma unroll
    for (int j = 0; j < 32; j += 4)
        *(float4*)&wrow[j] = *(const float4*)&w_out[(long)o * 256 + h * 32 + j];
    float acc[32];
#pragma unroll
    for (int d = 0; d < 32; d++) acc[d] = 0.0f;
#pragma unroll 8
    for (int e = 0; e < 32; e++) {
        float we = wrow[e];
#pragma unroll
        for (int d = 0; d < 32; d++) acc[d] += we * Cs[d][e];
    }
    long ub = (long)b * CD * KD + (long)o * KD + h * 32;
#pragma unroll
    for (int d = 0; d < 32; d++) {
        __half hi, lo;
        split_h(acc[d] * s_inv[d], hi, lo);
        g_u_hi[ub + d] = hi;
        g_u_lo[ub + d] = lo;
    }
}

// ------------------------- launch ------------------------------------------
extern "C" void kernel_launch(void* const* d_in, const int* in_sizes, int n_in,
                              void* d_out, int out_size)
{
    const float* x     = (const float*)d_in[0];
    const float* w_qkv = (const float*)d_in[1];
    const float* w_out = (const float*)d_in[2];
    const float* b_out = (const float*)d_in[3];
    float* y = (float*)d_out;

    cudaFuncSetAttribute(gemm_mma<0>, cudaFuncAttributeMaxDynamicSharedMemorySize, SMEM_BYTES);
    cudaFuncSetAttribute(gemm_mma<1>, cudaFuncAttributeMaxDynamicSharedMemorySize, SMEM_BYTES);
    cudaFuncSetAttribute(gemm_mma<2>, cudaFuncAttributeMaxDynamicSharedMemorySize, SMEM_BYTES);
    cudaFuncSetAttribute(ctx_mma, cudaFuncAttributeMaxDynamicSharedMemorySize, CSMEM_BYTES);

    __half *xt_hi, *xt_lo, *wkv_hi, *wkv_lo, *wqt_hi, *wqt_lo;
    __half *u_hi, *u_lo, *weff_hi, *weff_lo, *ekv_hi, *ekv_lo;
    cudaGetSymbolAddress((void**)&xt_hi, g_xt_hi);
    cudaGetSymbolAddress((void**)&xt_lo, g_xt_lo);
    cudaGetSymbolAddress((void**)&wkv_hi, g_wkv_hi);
    cudaGetSymbolAddress((void**)&wkv_lo, g_wkv_lo);
    cudaGetSymbolAddress((void**)&wqt_hi, g_wqt_hi);
    cudaGetSymbolAddress((void**)&wqt_lo, g_wqt_lo);
    cudaGetSymbolAddress((void**)&u_hi, g_u_hi);
    cudaGetSymbolAddress((void**)&u_lo, g_u_lo);
    cudaGetSymbolAddress((void**)&weff_hi, g_weff_hi);
    cudaGetSymbolAddress((void**)&weff_lo, g_weff_lo);
    cudaGetSymbolAddress((void**)&ekv_hi, g_ekv_hi);
    cudaGetSymbolAddress((void**)&ekv_lo, g_ekv_lo);

    // 1) conversions
    conv_x<<<dim3(NPIX / 32, NB), 256>>>(x);
    conv_wkv<<<512, 256>>>(w_qkv);
    conv_wqt<<<dim3(8, 8), 256>>>(w_qkv);

    // 2a) K half: expK = exp(wkv_K @ xT^T), 3-pass + exp (rows 0-255)
    gemm_mma<2><<<dim3(NPIX / 128, 2, NB), 256, SMEM_BYTES>>>(
        wkv_hi, wkv_lo, 0L, xt_hi, xt_lo, (long)NPIX * CD,
        nullptr, ekv_hi, ekv_lo, (long)512 * NPIX, NPIX, nullptr);

    // 2b) V half: V = wkv_V @ xT^T, 2-pass (rows 256-511; x_lo never loaded)
    gemm_mma<1><<<dim3(NPIX / 128, 2, NB), 256, SMEM_BYTES>>>(
        wkv_hi + 256 * KD, wkv_lo + 256 * KD, 0L, xt_hi, nullptr, (long)NPIX * CD,
        nullptr, ekv_hi + (long)256 * NPIX, ekv_lo + (long)256 * NPIX,
        (long)512 * NPIX, NPIX, nullptr);

    // 3) C (+ row sums) = expK @ Vpad^T, tensor-core, 3-pass
    ctx_mma<<<dim3(8, NB), 256, CSMEM_BYTES>>>();

    // 4) normalize + U = w_out @ blockdiag(C^T)
    u_kernel<<<dim3(8, NB), 256>>>(w_out);

    // 5) weff = U @ WqT^T, 2-pass (M=256, N=256) -> fp16 hi/lo
    gemm_mma<1><<<dim3(2, 2, NB), 256, SMEM_BYTES>>>(
        u_hi, u_lo, (long)CD * KD, wqt_hi, nullptr, 0L,
        nullptr, weff_hi, weff_lo, (long)CD * KD, KD, nullptr);

    // 6) y = weff @ xT^T + b_out, 2-pass (M=256, N=4096 per batch)
    gemm_mma<0><<<dim3(NPIX / 128, 2, NB), 256, SMEM_BYTES>>>(
        weff_hi, weff_lo, (long)CD * KD, xt_hi, nullptr, (long)NPIX * CD,
        y, nullptr, nullptr, (long)CD * NPIX, NPIX, b_out);
}

// round 16
// speedup vs baseline: 1.6203x; 1.1117x over previous
#include <cuda_runtime.h>
#include <cuda_fp16.h>
#include <cstdint>

// ===========================================================================
// LinearAttention via mma.sync fp16 split-precision, all-2-pass edition.
// R16 = R15 + smem-size fix: SMEM_BYTES must cover the hi/lo epilogue staging
//       area (69,632 B), which the 3-tile pipeline (61,440 B) no longer did.
// ===========================================================================

#define NB   16
#define NPIX 4096
#define CD   256
#define KD   256

__device__ __half g_xt_hi[(long)NB * NPIX * CD];
__device__ __half g_wkv_hi[512 * KD];
__device__ __half g_wkv_lo[512 * KD];
__device__ __half g_wqt_hi[CD * KD];
__device__ __half g_ekv_hi[(long)NB * 512 * NPIX];  // exp(K) rows 0-255, V rows 256-511
__device__ __half g_ekv_lo[(long)NB * 512 * NPIX];  // only K rows (0-255) ever written/read
__device__ float g_C[NB * 8 * 32 * 33];             // C[32x32] + S col at 32
__device__ __half g_u_hi[NB * CD * KD];
__device__ __half g_u_lo[NB * CD * KD];
__device__ __half g_weff_hi[NB * CD * KD];
__device__ __half g_weff_lo[NB * CD * KD];

// ------------------------- helpers ----------------------------------------
__device__ __forceinline__ uint32_t smem_u32(const void* p) {
    uint32_t a;
    asm("{ .reg .u64 t; cvta.to.shared.u64 t, %1; cvt.u32.u64 %0, t; }"
        : "=r"(a) : "l"(p));
    return a;
}
__device__ __forceinline__ void ldsm_x4(uint32_t* r, uint32_t addr) {
    asm volatile("ldmatrix.sync.aligned.m8n8.x4.shared.b16 {%0,%1,%2,%3}, [%4];"
                 : "=r"(r[0]), "=r"(r[1]), "=r"(r[2]), "=r"(r[3]) : "r"(addr));
}
__device__ __forceinline__ void mma_f16(float* d, const uint32_t* a, const uint32_t* b) {
    asm volatile(
        "mma.sync.aligned.m16n8k16.row.col.f32.f16.f16.f32 "
        "{%0,%1,%2,%3}, {%4,%5,%6,%7}, {%8,%9}, {%0,%1,%2,%3};"
        : "+f"(d[0]), "+f"(d[1]), "+f"(d[2]), "+f"(d[3])
        : "r"(a[0]), "r"(a[1]), "r"(a[2]), "r"(a[3]), "r"(b[0]), "r"(b[1]));
}
__device__ __forceinline__ void cp_async16(uint32_t smem_dst, const void* gsrc) {
    asm volatile("cp.async.ca.shared.global [%0], [%1], 16;"
                 :: "r"(smem_dst), "l"(gsrc) : "memory");
}
__device__ __forceinline__ void cp_commit() {
    asm volatile("cp.async.commit_group;" ::: "memory");
}
template <int N>
__device__ __forceinline__ void cp_wait() {
    asm volatile("cp.async.wait_group %0;" :: "n"(N) : "memory");
}
__device__ __forceinline__ void split_h(float v, __half& hi, __half& lo) {
    hi = __float2half(v);
    lo = __float2half(v - __half2float(hi));
}

// ------------------------- conversion kernels ------------------------------
__global__ void __launch_bounds__(256) conv_x(const float* __restrict__ x) {
    __shared__ float sb[32][257];
    const int b = blockIdx.y, n0 = blockIdx.x * 32;
    const float* xb = x + (long)b * CD * NPIX;
    const int tn = threadIdx.x & 31, tc = threadIdx.x >> 5;

#pragma unroll
    for (int c0 = 0; c0 < 256; c0 += 8) {
        sb[tn][c0 + tc] = xb[(long)(c0 + tc) * NPIX + n0 + tn];
    }
    __syncthreads();

    const long base = (long)b * NPIX * CD;
    const int c = threadIdx.x;
#pragma unroll 4
    for (int i = 0; i < 32; i++) {
        g_xt_hi[base + (long)(n0 + i) * CD + c] = __float2half(sb[i][c]);
    }
}

__global__ void __launch_bounds__(256) conv_wkv(const float* __restrict__ w_qkv) {
    int i = blockIdx.x * 256 + threadIdx.x;
    float v = w_qkv[256 * 256 + i];
    __half hi, lo;
    split_h(v, hi, lo);
    g_wkv_hi[i] = hi;
    g_wkv_lo[i] = lo;
}

__global__ void __launch_bounds__(256) conv_wqt(const float* __restrict__ w_qkv) {
    __shared__ float t[32][33];
    const int t0 = blockIdx.x * 32, c0 = blockIdx.y * 32;
    const int tn = threadIdx.x & 31, tr = threadIdx.x >> 5;
#pragma unroll
    for (int i = 0; i < 32; i += 8)
        t[tr + i][tn] = w_qkv[(long)(t0 + tr + i) * 256 + c0 + tn];
    __syncthreads();
#pragma unroll
    for (int i = 0; i < 32; i += 8) {
        long idx = (long)(c0 + tr + i) * KD + t0 + tn;
        g_wqt_hi[idx] = __float2half(t[tn][tr + i]);
    }
}

// ------------------------- warp-MMA GEMM (cp.async 2-stage, 2-pass) --------
// Block tile 128x128, BK=32, 8 warps of 64x32. D = (Ahi+Alo) @ Bhi^T.
// OUT_MODE 0: fp32+bias. 1: fp16 hi/lo. 2: fp16 hi/lo + exp(). 3: fp16 hi only.
#define BK   32
#define LDS  40
#define TILE_ELE (128 * LDS)
#define STAGE_ELE (3 * TILE_ELE)
#define PIPE_BYTES (2 * STAGE_ELE * 2)          // 61,440 B
#define EPI_BYTES  (2 * 128 * 68 * 4)           // 69,632 B (hi+lo staging)
#define SMEM_BYTES ((PIPE_BYTES > EPI_BYTES) ? PIPE_BYTES : EPI_BYTES)

template <int OUT_MODE>
__global__ void __launch_bounds__(256, 2) gemm_mma(
    const __half* __restrict__ Ahi, const __half* __restrict__ Alo, long sA,
    const __half* __restrict__ Bhi, long sB,
    float* __restrict__ Cf, __half* __restrict__ Chi, __half* __restrict__ Clo,
    long sC, int ldc, const float* __restrict__ bias)
{
    extern __shared__ __align__(16) __half sm[];

    const int tid = threadIdx.x, wid = tid >> 5, lane = tid & 31;
    const int warp_m = wid >> 2, warp_n = wid & 3;
    const int b = blockIdx.z;
    const int m0 = blockIdx.y * 128, n0 = blockIdx.x * 128;

    const __half* srcs[3] = {
        Ahi + (long)b * sA + (long)m0 * KD,
        Alo + (long)b * sA + (long)m0 * KD,
        Bhi + (long)b * sB + (long)n0 * KD};

    const uint32_t smb = smem_u32(sm);

    const int ldrow = tid >> 1;
    const int ldseg = (tid & 1) * 8;

    auto prefetch = [&](int kc, int stage) {
        const int k0 = kc * BK;
        const uint32_t sbase = smb + (uint32_t)stage * STAGE_ELE * 2;
#pragma unroll
        for (int t4 = 0; t4 < 3; t4++) {
            const __half* s = srcs[t4] + (long)ldrow * KD + k0 + ldseg;
            const uint32_t d = sbase + (uint32_t)(t4 * TILE_ELE + ldrow * LDS + ldseg) * 2;
            cp_async16(d, s);
            cp_async16(d + 32, s + 16);
        }
        cp_commit();
    };

    float acc[4][4][4];
#pragma unroll
    for (int i = 0; i < 4; i++)
#pragma unroll
        for (int j = 0; j < 4; j++)
#pragma unroll
            for (int k = 0; k < 4; k++) acc[i][j][k] = 0.0f;

    prefetch(0, 0);

    for (int kc = 0; kc < 8; kc++) {
        cp_wait<0>();
        __syncthreads();
        if (kc + 1 < 8) prefetch(kc + 1, (kc + 1) & 1);

        const uint32_t sbase = smb + (uint32_t)(kc & 1) * STAGE_ELE * 2;
#pragma unroll
        for (int ks = 0; ks < 2; ks++) {
            const int kk = ks * 16;
            uint32_t ahi[4][4], alo[4][4];
#pragma unroll
            for (int mf = 0; mf < 4; mf++) {
                const int am = warp_m * 64 + mf * 16 + (lane & 15);
                const uint32_t off = (uint32_t)(am * LDS + kk + (lane >> 4) * 8) * 2;
                ldsm_x4(ahi[mf], sbase + (0 * TILE_ELE) * 2 + off);
                ldsm_x4(alo[mf], sbase + (1 * TILE_ELE) * 2 + off);
            }
#pragma unroll
            for (int np = 0; np < 2; np++) {
                uint32_t bhi[4];
                const int bn = warp_n * 32 + np * 16 + ((lane & 16) >> 1) + (lane & 7);
                const uint32_t off = (uint32_t)(bn * LDS + kk + (lane & 8)) * 2;
                ldsm_x4(bhi, sbase + (2 * TILE_ELE) * 2 + off);
                // Pass 1: Ahi x Bhi
#pragma unroll
                for (int mf = 0; mf < 4; mf++)
#pragma unroll
                    for (int h = 0; h < 2; h++)
                        mma_f16(acc[mf][np * 2 + h], ahi[mf], &bhi[h * 2]);
                // Pass 2: Alo x Bhi
#pragma unroll
                for (int mf = 0; mf < 4; mf++)
#pragma unroll
                    for (int h = 0; h < 2; h++)
                        mma_f16(acc[mf][np * 2 + h], alo[mf], &bhi[h * 2]);
            }
        }
        __syncthreads();
    }

    // ---- epilogue ----
    if (OUT_MODE == 0) {
#pragma unroll
        for (int mf = 0; mf < 4; mf++) {
            const int row0 = m0 + warp_m * 64 + mf * 16 + (lane >> 2);
#pragma unroll
            for (int half_i = 0; half_i < 2; half_i++) {
                const int m = row0 + half_i * 8;
                const float bb = bias ? bias[m] : 0.0f;
                float* dst = Cf + (long)b * sC + (long)m * ldc + n0 + warp_n * 32 + (lane & 3) * 2;
#pragma unroll
                for (int nf = 0; nf < 4; nf++) {
                    float2 v;
                    v.x = acc[mf][nf][half_i * 2 + 0] + bb;
                    v.y = acc[mf][nf][half_i * 2 + 1] + bb;
                    *(float2*)(dst + nf * 8) = v;
                }
            }
        }
    } else {
        // Stage packed half2 through smem; then coalesced 16B stores.
        constexpr bool WRITE_LO = (OUT_MODE != 3);
        uint32_t* s_hi = (uint32_t*)sm;
        uint32_t* s_lo = s_hi + 128 * 68;   // covered by EPI_BYTES
        const bool do_exp = (OUT_MODE == 2);
#pragma unroll
        for (int mf = 0; mf < 4; mf++) {
#pragma unroll
            for (int half_i = 0; half_i < 2; half_i++) {
                const int r = warp_m * 64 + mf * 16 + (lane >> 2) + half_i * 8;
#pragma unroll
                for (int nf = 0; nf < 4; nf++) {
                    float v0 = acc[mf][nf][half_i * 2 + 0];
                    float v1 = acc[mf][nf][half_i * 2 + 1];
                    if (do_exp) { v0 = __expf(v0); v1 = __expf(v1); }
                    const int cw = warp_n * 16 + nf * 4 + (lane & 3);
                    if (WRITE_LO) {
                        __half h0, l0, h1, l1;
                        split_h(v0, h0, l0);
                        split_h(v1, h1, l1);
                        s_hi[r * 68 + cw] =
                            ((uint32_t)__half_as_ushort(h1) << 16) | __half_as_ushort(h0);
                        s_lo[r * 68 + cw] =
                            ((uint32_t)__half_as_ushort(l1) << 16) | __half_as_ushort(l0);
                    } else {
                        __half h0 = __float2half(v0), h1 = __float2half(v1);
                        s_hi[r * 68 + cw] =
                            ((uint32_t)__half_as_ushort(h1) << 16) | __half_as_ushort(h0);
                    }
                }
            }
        }
        __syncthreads();
        for (int i = tid; i < 128 * 16; i += 256) {
            const int r = i >> 4, seg = i & 15;
            long off = (long)b * sC + (long)(m0 + r) * ldc + n0 + seg * 8;
            uint4 vh = *(uint4*)&s_hi[r * 68 + seg * 4];
            *(uint4*)(Chi + off) = vh;
            if (WRITE_LO) {
                uint4 vl = *(uint4*)&s_lo[r * 68 + seg * 4];
                *(uint4*)(Clo + off) = vl;
            }
        }
    }
}

// ------------------------- ctx via mma (2-pass) -----------------------------
// Per (b,h): C[32x48] = (expKhi+expKlo)(32x4096) @ Bpad^T, Bpad rows 0-31 = V_hi,
// row 32 = ones -> exact row sums, rows 33-47 = zero.
#define CBK 128
#define CLDS 136
#define CA_ELE (32 * CLDS)
#define CB_ELE (48 * CLDS)
#define CSTAGE_ELE (2 * CA_ELE + CB_ELE)
#define CSMEM_BYTES (2 * CSTAGE_ELE * 2)   // 60,928 B; fp32 reduction (49,152) fits

__global__ void __launch_bounds__(256) ctx_mma() {
    extern __shared__ __align__(16) __half csm[];
    const int h = blockIdx.x, b = blockIdx.y;
    const int tid = threadIdx.x, wid = tid >> 5, lane = tid & 31;

    const __half* srcs[3] = {
        g_ekv_hi + ((long)b * 512 + h * 32) * NPIX,         // expK hi
        g_ekv_lo + ((long)b * 512 + h * 32) * NPIX,         // expK lo
        g_ekv_hi + ((long)b * 512 + 256 + h * 32) * NPIX};  // V hi
    const uint32_t offs[3] = {0, CA_ELE, 2 * CA_ELE};

    const uint32_t smb = smem_u32(csm);

    const __half one = __float2half(1.0f);
    const __half zero = __float2half(0.0f);
    for (int s = 0; s < 2; s++) {
        __half* Bh = csm + s * CSTAGE_ELE + 2 * CA_ELE + 32 * CLDS;
        for (int i = tid; i < 16 * CLDS; i += 256)
            Bh[i] = (i < CLDS) ? one : zero;
    }

    const int lrow = tid >> 3;
    const int lseg = (tid & 7) * 16;

    auto prefetch = [&](int kc, int stage) {
        const int k0 = kc * CBK;
        const uint32_t sbase = smb + (uint32_t)stage * CSTAGE_ELE * 2;
#pragma unroll
        for (int t4 = 0; t4 < 3; t4++) {
            const __half* s = srcs[t4] + (long)lrow * NPIX + k0 + lseg;
            const uint32_t d = sbase + (uint32_t)(offs[t4] + lrow * CLDS + lseg) * 2;
            cp_async16(d, s);
            cp_async16(d + 16, s + 8);
        }
        cp_commit();
    };

    float acc[2][6][4];
#pragma unroll
    for (int i = 0; i < 2; i++)
#pragma unroll
        for (int j = 0; j < 6; j++)
#pragma unroll
            for (int k = 0; k < 4; k++) acc[i][j][k] = 0.0f;

    prefetch(0, 0);

    const int kk = wid * 16;
    for (int kc = 0; kc < NPIX / CBK; kc++) {
        cp_wait<0>();
        __syncthreads();
        if (kc + 1 < NPIX / CBK) prefetch(kc + 1, (kc + 1) & 1);

        const uint32_t sbase = smb + (uint32_t)(kc & 1) * CSTAGE_ELE * 2;
        uint32_t ahi[2][4], alo[2][4];
#pragma unroll
        for (int mf = 0; mf < 2; mf++) {
            const int am = mf * 16 + (lane & 15);
            const uint32_t off = (uint32_t)(am * CLDS + kk + (lane >> 4) * 8) * 2;
            ldsm_x4(ahi[mf], sbase + off);
            ldsm_x4(alo[mf], sbase + CA_ELE * 2 + off);
        }
#pragma unroll
        for (int np = 0; np < 3; np++) {
            uint32_t bhi[4];
            const int bn = np * 16 + ((lane & 16) >> 1) + (lane & 7);
            const uint32_t off = (uint32_t)(bn * CLDS + kk + (lane & 8)) * 2;
            ldsm_x4(bhi, sbase + 2 * CA_ELE * 2 + off);
#pragma unroll
            for (int mf = 0; mf < 2; mf++)
#pragma unroll
                for (int hh = 0; hh < 2; hh++) {
                    float* a = acc[mf][np * 2 + hh];
                    mma_f16(a, ahi[mf], &bhi[hh * 2]);
                    mma_f16(a, alo[mf], &bhi[hh * 2]);
                }
        }
        __syncthreads();
    }

    // ---- cross-warp reduction (reuse smem as fp32 [8][32][48]) ----
    float* red = (float*)csm;
#pragma unroll
    for (int mf = 0; mf < 2; mf++)
#pragma unroll
        for (int nf = 0; nf < 6; nf++)
#pragma unroll
            for (int i = 0; i < 4; i++) {
                int row = mf * 16 + (lane >> 2) + (i >> 1) * 8;
                int col = nf * 8 + (lane & 3) * 2 + (i & 1);
                red[((long)wid * 32 + row) * 48 + col] = acc[mf][nf][i];
            }
    __syncthreads();

    float* Cp = g_C + ((long)(b * 8 + h)) * 32 * 33;
    for (int o = tid; o < 32 * 48; o += 256) {
        int row = o / 48, col = o % 48;
        float s = 0.0f;
#pragma unroll
        for (int w = 0; w < 8; w++) s += red[((long)w * 32 + row) * 48 + col];
        if (col < 33) Cp[row * 33 + col] = s;
    }
}

// U = w_out @ blockdiag((C/S)^T), write fp16 hi/lo
__global__ void __launch_bounds__(256) u_kernel(const float* __restrict__ w_out) {
    const int h = blockIdx.x, b = blockIdx.y;
    __shared__ float Cs[32][33];
    __shared__ float s_inv[32];
    const int tid = threadIdx.x;
    const float* Cp = g_C + ((long)(b * 8 + h)) * 32 * 33;

    if (tid < 32) s_inv[tid] = 1.0f / Cp[tid * 33 + 32];
    for (int t = tid; t < 32 * 33; t += 256) Cs[t / 33][t % 33] = Cp[t];
    __syncthreads();

    const int o = tid;
    float wrow[32];
#pragma unroll
    for (int j = 0; j < 32; j += 4)
        *(float4*)&wrow[j] = *(const float4*)&w_out[(long)o * 256 + h * 32 + j];
    float acc[32];
#pragma unroll
    for (int d = 0; d < 32; d++) acc[d] = 0.0f;
#pragma unroll 8
    for (int e = 0; e < 32; e++) {
        float we = wrow[e];
#pragma unroll
        for (int d = 0; d < 32; d++) acc[d] += we * Cs[d][e];
    }
    long ub = (long)b * CD * KD + (long)o * KD + h * 32;
#pragma unroll
    for (int d = 0; d < 32; d++) {
        __half hi, lo;
        split_h(acc[d] * s_inv[d], hi, lo);
        g_u_hi[ub + d] = hi;
        g_u_lo[ub + d] = lo;
    }
}

// ------------------------- launch ------------------------------------------
extern "C" void kernel_launch(void* const* d_in, const int* in_sizes, int n_in,
                              void* d_out, int out_size)
{
    const float* x     = (const float*)d_in[0];
    const float* w_qkv = (const float*)d_in[1];
    const float* w_out = (const float*)d_in[2];
    const float* b_out = (const float*)d_in[3];
    float* y = (float*)d_out;

    cudaFuncSetAttribute(gemm_mma<0>, cudaFuncAttributeMaxDynamicSharedMemorySize, SMEM_BYTES);
    cudaFuncSetAttribute(gemm_mma<1>, cudaFuncAttributeMaxDynamicSharedMemorySize, SMEM_BYTES);
    cudaFuncSetAttribute(gemm_mma<2>, cudaFuncAttributeMaxDynamicSharedMemorySize, SMEM_BYTES);
    cudaFuncSetAttribute(gemm_mma<3>, cudaFuncAttributeMaxDynamicSharedMemorySize, SMEM_BYTES);
    cudaFuncSetAttribute(ctx_mma, cudaFuncAttributeMaxDynamicSharedMemorySize, CSMEM_BYTES);

    __half *xt_hi, *wkv_hi, *wkv_lo, *wqt_hi;
    __half *u_hi, *u_lo, *weff_hi, *weff_lo, *ekv_hi, *ekv_lo;
    cudaGetSymbolAddress((void**)&xt_hi, g_xt_hi);
    cudaGetSymbolAddress((void**)&wkv_hi, g_wkv_hi);
    cudaGetSymbolAddress((void**)&wkv_lo, g_wkv_lo);
    cudaGetSymbolAddress((void**)&wqt_hi, g_wqt_hi);
    cudaGetSymbolAddress((void**)&u_hi, g_u_hi);
    cudaGetSymbolAddress((void**)&u_lo, g_u_lo);
    cudaGetSymbolAddress((void**)&weff_hi, g_weff_hi);
    cudaGetSymbolAddress((void**)&weff_lo, g_weff_lo);
    cudaGetSymbolAddress((void**)&ekv_hi, g_ekv_hi);
    cudaGetSymbolAddress((void**)&ekv_lo, g_ekv_lo);

    // 1) conversions (x_lo never materialized)
    conv_x<<<dim3(NPIX / 32, NB), 256>>>(x);
    conv_wkv<<<512, 256>>>(w_qkv);
    conv_wqt<<<dim3(8, 8), 256>>>(w_qkv);

    // 2a) K half: expK = exp((wkv_hi+wkv_lo) @ xt_hi^T), 2-pass + exp
    gemm_mma<2><<<dim3(NPIX / 128, 2, NB), 256, SMEM_BYTES>>>(
        wkv_hi, wkv_lo, 0L, xt_hi, (long)NPIX * CD,
        nullptr, ekv_hi, ekv_lo, (long)512 * NPIX, NPIX, nullptr);

    // 2b) V half: V_hi = (wkv_hi+wkv_lo)_V @ xt_hi^T, 2-pass, hi-only out
    gemm_mma<3><<<dim3(NPIX / 128, 2, NB), 256, SMEM_BYTES>>>(
        wkv_hi + 256 * KD, wkv_lo + 256 * KD, 0L, xt_hi, (long)NPIX * CD,
        nullptr, ekv_hi + (long)256 * NPIX, nullptr,
        (long)512 * NPIX, NPIX, nullptr);

    // 3) C (+ exact row sums) = expK @ Vpad^T, 2-pass
    ctx_mma<<<dim3(8, NB), 256, CSMEM_BYTES>>>();

    // 4) normalize + U = w_out @ blockdiag(C^T)
    u_kernel<<<dim3(8, NB), 256>>>(w_out);

    // 5) weff = (U_hi+U_lo) @ wqt_hi^T, 2-pass -> fp16 hi/lo
    gemm_mma<1><<<dim3(2, 2, NB), 256, SMEM_BYTES>>>(
        u_hi, u_lo, (long)CD * KD, wqt_hi, 0L,
        nullptr, weff_hi, weff_lo, (long)CD * KD, KD, nullptr);

    // 6) y = (weff_hi+weff_lo) @ xt_hi^T + b_out, 2-pass
    gemm_mma<0><<<dim3(NPIX / 128, 2, NB), 256, SMEM_BYTES>>>(
        weff_hi, weff_lo, (long)CD * KD, xt_hi, (long)NPIX * CD,
        y, nullptr, nullptr, (long)CD * NPIX, NPIX, b_out);
}

// round 17
// speedup vs baseline: 1.8853x; 1.1636x over previous
#include <cuda_runtime.h>
#include <cuda_fp16.h>
#include <cstdint>

// ===========================================================================
// LinearAttention via mma.sync fp16 split-precision.
// R17 = R16 + NPASS template: V-half and y-GEMM go 1-pass (Alo tile never
//       loaded, half the MMAs); weff output hi-only (weff_lo now dead).
//       K stays 2-pass (exp path keeps precision), ctx unchanged.
// ===========================================================================

#define NB   16
#define NPIX 4096
#define CD   256
#define KD   256

__device__ __half g_xt_hi[(long)NB * NPIX * CD];
__device__ __half g_wkv_hi[512 * KD];
__device__ __half g_wkv_lo[512 * KD];
__device__ __half g_wqt_hi[CD * KD];
__device__ __half g_ekv_hi[(long)NB * 512 * NPIX];  // exp(K) rows 0-255, V rows 256-511
__device__ __half g_ekv_lo[(long)NB * 512 * NPIX];  // only K rows (0-255) written/read
__device__ float g_C[NB * 8 * 32 * 33];             // C[32x32] + S col at 32
__device__ __half g_u_hi[NB * CD * KD];
__device__ __half g_u_lo[NB * CD * KD];
__device__ __half g_weff_hi[NB * CD * KD];

// ------------------------- helpers ----------------------------------------
__device__ __forceinline__ uint32_t smem_u32(const void* p) {
    uint32_t a;
    asm("{ .reg .u64 t; cvta.to.shared.u64 t, %1; cvt.u32.u64 %0, t; }"
        : "=r"(a) : "l"(p));
    return a;
}
__device__ __forceinline__ void ldsm_x4(uint32_t* r, uint32_t addr) {
    asm volatile("ldmatrix.sync.aligned.m8n8.x4.shared.b16 {%0,%1,%2,%3}, [%4];"
                 : "=r"(r[0]), "=r"(r[1]), "=r"(r[2]), "=r"(r[3]) : "r"(addr));
}
__device__ __forceinline__ void mma_f16(float* d, const uint32_t* a, const uint32_t* b) {
    asm volatile(
        "mma.sync.aligned.m16n8k16.row.col.f32.f16.f16.f32 "
        "{%0,%1,%2,%3}, {%4,%5,%6,%7}, {%8,%9}, {%0,%1,%2,%3};"
        : "+f"(d[0]), "+f"(d[1]), "+f"(d[2]), "+f"(d[3])
        : "r"(a[0]), "r"(a[1]), "r"(a[2]), "r"(a[3]), "r"(b[0]), "r"(b[1]));
}
__device__ __forceinline__ void cp_async16(uint32_t smem_dst, const void* gsrc) {
    asm volatile("cp.async.ca.shared.global [%0], [%1], 16;"
                 :: "r"(smem_dst), "l"(gsrc) : "memory");
}
__device__ __forceinline__ void cp_commit() {
    asm volatile("cp.async.commit_group;" ::: "memory");
}
template <int N>
__device__ __forceinline__ void cp_wait() {
    asm volatile("cp.async.wait_group %0;" :: "n"(N) : "memory");
}
__device__ __forceinline__ void split_h(float v, __half& hi, __half& lo) {
    hi = __float2half(v);
    lo = __float2half(v - __half2float(hi));
}

// ------------------------- conversion kernels ------------------------------
__global__ void __launch_bounds__(256) conv_x(const float* __restrict__ x) {
    __shared__ float sb[32][257];
    const int b = blockIdx.y, n0 = blockIdx.x * 32;
    const float* xb = x + (long)b * CD * NPIX;
    const int tn = threadIdx.x & 31, tc = threadIdx.x >> 5;

#pragma unroll
    for (int c0 = 0; c0 < 256; c0 += 8) {
        sb[tn][c0 + tc] = xb[(long)(c0 + tc) * NPIX + n0 + tn];
    }
    __syncthreads();

    const long base = (long)b * NPIX * CD;
    const int c = threadIdx.x;
#pragma unroll 4
    for (int i = 0; i < 32; i++) {
        g_xt_hi[base + (long)(n0 + i) * CD + c] = __float2half(sb[i][c]);
    }
}

__global__ void __launch_bounds__(256) conv_wkv(const float* __restrict__ w_qkv) {
    int i = blockIdx.x * 256 + threadIdx.x;
    float v = w_qkv[256 * 256 + i];
    __half hi, lo;
    split_h(v, hi, lo);
    g_wkv_hi[i] = hi;
    g_wkv_lo[i] = lo;
}

__global__ void __launch_bounds__(256) conv_wqt(const float* __restrict__ w_qkv) {
    __shared__ float t[32][33];
    const int t0 = blockIdx.x * 32, c0 = blockIdx.y * 32;
    const int tn = threadIdx.x & 31, tr = threadIdx.x >> 5;
#pragma unroll
    for (int i = 0; i < 32; i += 8)
        t[tr + i][tn] = w_qkv[(long)(t0 + tr + i) * 256 + c0 + tn];
    __syncthreads();
#pragma unroll
    for (int i = 0; i < 32; i += 8) {
        long idx = (long)(c0 + tr + i) * KD + t0 + tn;
        g_wqt_hi[idx] = __float2half(t[tn][tr + i]);
    }
}

// ------------------------- warp-MMA GEMM (cp.async 2-stage) ----------------
// Block tile 128x128, BK=32, 8 warps of 64x32.
// NPASS=2: D = (Ahi+Alo) @ Bhi^T.  NPASS=1: D = Ahi @ Bhi^T (Alo never loaded).
// OUT_MODE 0: fp32+bias. 1: fp16 hi/lo. 2: fp16 hi/lo + exp(). 3: fp16 hi only.
#define BK   32
#define LDS  40
#define TILE_ELE (128 * LDS)
#define STAGE_ELE (3 * TILE_ELE)
#define PIPE_BYTES (2 * STAGE_ELE * 2)          // 61,440 B
#define EPI_BYTES  (2 * 128 * 68 * 4)           // 69,632 B (hi+lo staging)
#define SMEM_BYTES ((PIPE_BYTES > EPI_BYTES) ? PIPE_BYTES : EPI_BYTES)

template <int OUT_MODE, int NPASS>
__global__ void __launch_bounds__(256, 2) gemm_mma(
    const __half* __restrict__ Ahi, const __half* __restrict__ Alo, long sA,
    const __half* __restrict__ Bhi, long sB,
    float* __restrict__ Cf, __half* __restrict__ Chi, __half* __restrict__ Clo,
    long sC, int ldc, const float* __restrict__ bias)
{
    extern __shared__ __align__(16) __half sm[];
    constexpr int NTILES = (NPASS == 2) ? 3 : 2;

    const int tid = threadIdx.x, wid = tid >> 5, lane = tid & 31;
    const int warp_m = wid >> 2, warp_n = wid & 3;
    const int b = blockIdx.z;
    const int m0 = blockIdx.y * 128, n0 = blockIdx.x * 128;

    // slot 0: Ahi, slot 1: Bhi, slot 2 (NPASS==2 only): Alo
    const __half* srcs[3];
    srcs[0] = Ahi + (long)b * sA + (long)m0 * KD;
    srcs[1] = Bhi + (long)b * sB + (long)n0 * KD;
    srcs[2] = (NPASS == 2) ? (Alo + (long)b * sA + (long)m0 * KD) : srcs[0];

    const uint32_t smb = smem_u32(sm);

    const int ldrow = tid >> 1;
    const int ldseg = (tid & 1) * 8;

    auto prefetch = [&](int kc, int stage) {
        const int k0 = kc * BK;
        const uint32_t sbase = smb + (uint32_t)stage * STAGE_ELE * 2;
#pragma unroll
        for (int t4 = 0; t4 < NTILES; t4++) {
            const __half* s = srcs[t4] + (long)ldrow * KD + k0 + ldseg;
            const uint32_t d = sbase + (uint32_t)(t4 * TILE_ELE + ldrow * LDS + ldseg) * 2;
            cp_async16(d, s);
            cp_async16(d + 32, s + 16);
        }
        cp_commit();
    };

    float acc[4][4][4];
#pragma unroll
    for (int i = 0; i < 4; i++)
#pragma unroll
        for (int j = 0; j < 4; j++)
#pragma unroll
            for (int k = 0; k < 4; k++) acc[i][j][k] = 0.0f;

    prefetch(0, 0);

    for (int kc = 0; kc < 8; kc++) {
        cp_wait<0>();
        __syncthreads();
        if (kc + 1 < 8) prefetch(kc + 1, (kc + 1) & 1);

        const uint32_t sbase = smb + (uint32_t)(kc & 1) * STAGE_ELE * 2;
#pragma unroll
        for (int ks = 0; ks < 2; ks++) {
            const int kk = ks * 16;
            uint32_t ahi[4][4], alo[4][4];
#pragma unroll
            for (int mf = 0; mf < 4; mf++) {
                const int am = warp_m * 64 + mf * 16 + (lane & 15);
                const uint32_t off = (uint32_t)(am * LDS + kk + (lane >> 4) * 8) * 2;
                ldsm_x4(ahi[mf], sbase + (0 * TILE_ELE) * 2 + off);
                if (NPASS == 2)
                    ldsm_x4(alo[mf], sbase + (2 * TILE_ELE) * 2 + off);
            }
#pragma unroll
            for (int np = 0; np < 2; np++) {
                uint32_t bhi[4];
                const int bn = warp_n * 32 + np * 16 + ((lane & 16) >> 1) + (lane & 7);
                const uint32_t off = (uint32_t)(bn * LDS + kk + (lane & 8)) * 2;
                ldsm_x4(bhi, sbase + (1 * TILE_ELE) * 2 + off);
                // Pass 1: Ahi x Bhi
#pragma unroll
                for (int mf = 0; mf < 4; mf++)
#pragma unroll
                    for (int h = 0; h < 2; h++)
                        mma_f16(acc[mf][np * 2 + h], ahi[mf], &bhi[h * 2]);
                // Pass 2: Alo x Bhi
                if (NPASS == 2) {
#pragma unroll
                    for (int mf = 0; mf < 4; mf++)
#pragma unroll
                        for (int h = 0; h < 2; h++)
                            mma_f16(acc[mf][np * 2 + h], alo[mf], &bhi[h * 2]);
                }
            }
        }
        __syncthreads();
    }

    // ---- epilogue ----
    if (OUT_MODE == 0) {
#pragma unroll
        for (int mf = 0; mf < 4; mf++) {
            const int row0 = m0 + warp_m * 64 + mf * 16 + (lane >> 2);
#pragma unroll
            for (int half_i = 0; half_i < 2; half_i++) {
                const int m = row0 + half_i * 8;
                const float bb = bias ? bias[m] : 0.0f;
                float* dst = Cf + (long)b * sC + (long)m * ldc + n0 + warp_n * 32 + (lane & 3) * 2;
#pragma unroll
                for (int nf = 0; nf < 4; nf++) {
                    float2 v;
                    v.x = acc[mf][nf][half_i * 2 + 0] + bb;
                    v.y = acc[mf][nf][half_i * 2 + 1] + bb;
                    *(float2*)(dst + nf * 8) = v;
                }
            }
        }
    } else {
        // Stage packed half2 through smem; then coalesced 16B stores.
        constexpr bool WRITE_LO = (OUT_MODE != 3);
        uint32_t* s_hi = (uint32_t*)sm;
        uint32_t* s_lo = s_hi + 128 * 68;   // covered by EPI_BYTES
        const bool do_exp = (OUT_MODE == 2);
#pragma unroll
        for (int mf = 0; mf < 4; mf++) {
#pragma unroll
            for (int half_i = 0; half_i < 2; half_i++) {
                const int r = warp_m * 64 + mf * 16 + (lane >> 2) + half_i * 8;
#pragma unroll
                for (int nf = 0; nf < 4; nf++) {
                    float v0 = acc[mf][nf][half_i * 2 + 0];
                    float v1 = acc[mf][nf][half_i * 2 + 1];
                    if (do_exp) { v0 = __expf(v0); v1 = __expf(v1); }
                    const int cw = warp_n * 16 + nf * 4 + (lane & 3);
                    if (WRITE_LO) {
                        __half h0, l0, h1, l1;
                        split_h(v0, h0, l0);
                        split_h(v1, h1, l1);
                        s_hi[r * 68 + cw] =
                            ((uint32_t)__half_as_ushort(h1) << 16) | __half_as_ushort(h0);
                        s_lo[r * 68 + cw] =
                            ((uint32_t)__half_as_ushort(l1) << 16) | __half_as_ushort(l0);
                    } else {
                        __half h0 = __float2half(v0), h1 = __float2half(v1);
                        s_hi[r * 68 + cw] =
                            ((uint32_t)__half_as_ushort(h1) << 16) | __half_as_ushort(h0);
                    }
                }
            }
        }
        __syncthreads();
        for (int i = tid; i < 128 * 16; i += 256) {
            const int r = i >> 4, seg = i & 15;
            long off = (long)b * sC + (long)(m0 + r) * ldc + n0 + seg * 8;
            uint4 vh = *(uint4*)&s_hi[r * 68 + seg * 4];
            *(uint4*)(Chi + off) = vh;
            if (WRITE_LO) {
                uint4 vl = *(uint4*)&s_lo[r * 68 + seg * 4];
                *(uint4*)(Clo + off) = vl;
            }
        }
    }
}

// ------------------------- ctx via mma (2-pass) -----------------------------
// Per (b,h): C[32x48] = (expKhi+expKlo)(32x4096) @ Bpad^T, Bpad rows 0-31 = V_hi,
// row 32 = ones -> exact row sums, rows 33-47 = zero.
#define CBK 128
#define CLDS 136
#define CA_ELE (32 * CLDS)
#define CB_ELE (48 * CLDS)
#define CSTAGE_ELE (2 * CA_ELE + CB_ELE)
#define CSMEM_BYTES (2 * CSTAGE_ELE * 2)

__global__ void __launch_bounds__(256) ctx_mma() {
    extern __shared__ __align__(16) __half csm[];
    const int h = blockIdx.x, b = blockIdx.y;
    const int tid = threadIdx.x, wid = tid >> 5, lane = tid & 31;

    const __half* srcs[3] = {
        g_ekv_hi + ((long)b * 512 + h * 32) * NPIX,
        g_ekv_lo + ((long)b * 512 + h * 32) * NPIX,
        g_ekv_hi + ((long)b * 512 + 256 + h * 32) * NPIX};
    const uint32_t offs[3] = {0, CA_ELE, 2 * CA_ELE};

    const uint32_t smb = smem_u32(csm);

    const __half one = __float2half(1.0f);
    const __half zero = __float2half(0.0f);
    for (int s = 0; s < 2; s++) {
        __half* Bh = csm + s * CSTAGE_ELE + 2 * CA_ELE + 32 * CLDS;
        for (int i = tid; i < 16 * CLDS; i += 256)
            Bh[i] = (i < CLDS) ? one : zero;
    }

    const int lrow = tid >> 3;
    const int lseg = (tid & 7) * 16;

    auto prefetch = [&](int kc, int stage) {
        const int k0 = kc * CBK;
        const uint32_t sbase = smb + (uint32_t)stage * CSTAGE_ELE * 2;
#pragma unroll
        for (int t4 = 0; t4 < 3; t4++) {
            const __half* s = srcs[t4] + (long)lrow * NPIX + k0 + lseg;
            const uint32_t d = sbase + (uint32_t)(offs[t4] + lrow * CLDS + lseg) * 2;
            cp_async16(d, s);
            cp_async16(d + 16, s + 8);
        }
        cp_commit();
    };

    float acc[2][6][4];
#pragma unroll
    for (int i = 0; i < 2; i++)
#pragma unroll
        for (int j = 0; j < 6; j++)
#pragma unroll
            for (int k = 0; k < 4; k++) acc[i][j][k] = 0.0f;

    prefetch(0, 0);

    const int kk = wid * 16;
    for (int kc = 0; kc < NPIX / CBK; kc++) {
        cp_wait<0>();
        __syncthreads();
        if (kc + 1 < NPIX / CBK) prefetch(kc + 1, (kc + 1) & 1);

        const uint32_t sbase = smb + (uint32_t)(kc & 1) * CSTAGE_ELE * 2;
        uint32_t ahi[2][4], alo[2][4];
#pragma unroll
        for (int mf = 0; mf < 2; mf++) {
            const int am = mf * 16 + (lane & 15);
            const uint32_t off = (uint32_t)(am * CLDS + kk + (lane >> 4) * 8) * 2;
            ldsm_x4(ahi[mf], sbase + off);
            ldsm_x4(alo[mf], sbase + CA_ELE * 2 + off);
        }
#pragma unroll
        for (int np = 0; np < 3; np++) {
            uint32_t bhi[4];
            const int bn = np * 16 + ((lane & 16) >> 1) + (lane & 7);
            const uint32_t off = (uint32_t)(bn * CLDS + kk + (lane & 8)) * 2;
            ldsm_x4(bhi, sbase + 2 * CA_ELE * 2 + off);
#pragma unroll
            for (int mf = 0; mf < 2; mf++)
#pragma unroll
                for (int hh = 0; hh < 2; hh++) {
                    float* a = acc[mf][np * 2 + hh];
                    mma_f16(a, ahi[mf], &bhi[hh * 2]);
                    mma_f16(a, alo[mf], &bhi[hh * 2]);
                }
        }
        __syncthreads();
    }

    // ---- cross-warp reduction (reuse smem as fp32 [8][32][48]) ----
    float* red = (float*)csm;
#pragma unroll
    for (int mf = 0; mf < 2; mf++)
#pragma unroll
        for (int nf = 0; nf < 6; nf++)
#pragma unroll
            for (int i = 0; i < 4; i++) {
                int row = mf * 16 + (lane >> 2) + (i >> 1) * 8;
                int col = nf * 8 + (lane & 3) * 2 + (i & 1);
                red[((long)wid * 32 + row) * 48 + col] = acc[mf][nf][i];
            }
    __syncthreads();

    float* Cp = g_C + ((long)(b * 8 + h)) * 32 * 33;
    for (int o = tid; o < 32 * 48; o += 256) {
        int row = o / 48, col = o % 48;
        float s = 0.0f;
#pragma unroll
        for (int w = 0; w < 8; w++) s += red[((long)w * 32 + row) * 48 + col];
        if (col < 33) Cp[row * 33 + col] = s;
    }
}

// U = w_out @ blockdiag((C/S)^T), write fp16 hi/lo
__global__ void __launch_bounds__(256) u_kernel(const float* __restrict__ w_out) {
    const int h = blockIdx.x, b = blockIdx.y;
    __shared__ float Cs[32][33];
    __shared__ float s_inv[32];
    const int tid = threadIdx.x;
    const float* Cp = g_C + ((long)(b * 8 + h)) * 32 * 33;

    if (tid < 32) s_inv[tid] = 1.0f / Cp[tid * 33 + 32];
    for (int t = tid; t < 32 * 33; t += 256) Cs[t / 33][t % 33] = Cp[t];
    __syncthreads();

    const int o = tid;
    float wrow[32];
#pragma unroll
    for (int j = 0; j < 32; j += 4)
        *(float4*)&wrow[j] = *(const float4*)&w_out[(long)o * 256 + h * 32 + j];
    float acc[32];
#pragma unroll
    for (int d = 0; d < 32; d++) acc[d] = 0.0f;
#pragma unroll 8
    for (int e = 0; e < 32; e++) {
        float we = wrow[e];
#pragma unroll
        for (int d = 0; d < 32; d++) acc[d] += we * Cs[d][e];
    }
    long ub = (long)b * CD * KD + (long)o * KD + h * 32;
#pragma unroll
    for (int d = 0; d < 32; d++) {
        __half hi, lo;
        split_h(acc[d] * s_inv[d], hi, lo);
        g_u_hi[ub + d] = hi;
        g_u_lo[ub + d] = lo;
    }
}

// ------------------------- launch ------------------------------------------
extern "C" void kernel_launch(void* const* d_in, const int* in_sizes, int n_in,
                              void* d_out, int out_size)
{
    const float* x     = (const float*)d_in[0];
    const float* w_qkv = (const float*)d_in[1];
    const float* w_out = (const float*)d_in[2];
    const float* b_out = (const float*)d_in[3];
    float* y = (float*)d_out;

    cudaFuncSetAttribute((const void*)gemm_mma<2, 2>, cudaFuncAttributeMaxDynamicSharedMemorySize, SMEM_BYTES);
    cudaFuncSetAttribute((const void*)gemm_mma<3, 1>, cudaFuncAttributeMaxDynamicSharedMemorySize, SMEM_BYTES);
    cudaFuncSetAttribute((const void*)gemm_mma<3, 2>, cudaFuncAttributeMaxDynamicSharedMemorySize, SMEM_BYTES);
    cudaFuncSetAttribute((const void*)gemm_mma<0, 1>, cudaFuncAttributeMaxDynamicSharedMemorySize, SMEM_BYTES);
    cudaFuncSetAttribute((const void*)ctx_mma, cudaFuncAttributeMaxDynamicSharedMemorySize, CSMEM_BYTES);

    __half *xt_hi, *wkv_hi, *wkv_lo, *wqt_hi;
    __half *u_hi, *u_lo, *weff_hi, *ekv_hi, *ekv_lo;
    cudaGetSymbolAddress((void**)&xt_hi, g_xt_hi);
    cudaGetSymbolAddress((void**)&wkv_hi, g_wkv_hi);
    cudaGetSymbolAddress((void**)&wkv_lo, g_wkv_lo);
    cudaGetSymbolAddress((void**)&wqt_hi, g_wqt_hi);
    cudaGetSymbolAddress((void**)&u_hi, g_u_hi);
    cudaGetSymbolAddress((void**)&u_lo, g_u_lo);
    cudaGetSymbolAddress((void**)&weff_hi, g_weff_hi);
    cudaGetSymbolAddress((void**)&ekv_hi, g_ekv_hi);
    cudaGetSymbolAddress((void**)&ekv_lo, g_ekv_lo);

    // 1) conversions
    conv_x<<<dim3(NPIX / 32, NB), 256>>>(x);
    conv_wkv<<<512, 256>>>(w_qkv);
    conv_wqt<<<dim3(8, 8), 256>>>(w_qkv);

    // 2a) K half: expK = exp((wkv_hi+wkv_lo) @ xt_hi^T), 2-pass + exp
    gemm_mma<2, 2><<<dim3(NPIX / 128, 2, NB), 256, SMEM_BYTES>>>(
        wkv_hi, wkv_lo, 0L, xt_hi, (long)NPIX * CD,
        nullptr, ekv_hi, ekv_lo, (long)512 * NPIX, NPIX, nullptr);

    // 2b) V half: V_hi = wkv_hi_V @ xt_hi^T, 1-pass, hi-only out
    gemm_mma<3, 1><<<dim3(NPIX / 128, 2, NB), 256, SMEM_BYTES>>>(
        wkv_hi + 256 * KD, nullptr, 0L, xt_hi, (long)NPIX * CD,
        nullptr, ekv_hi + (long)256 * NPIX, nullptr,
        (long)512 * NPIX, NPIX, nullptr);

    // 3) C (+ exact row sums) = expK @ Vpad^T, 2-pass
    ctx_mma<<<dim3(8, NB), 256, CSMEM_BYTES>>>();

    // 4) normalize + U = w_out @ blockdiag(C^T)
    u_kernel<<<dim3(8, NB), 256>>>(w_out);

    // 5) weff_hi = (U_hi+U_lo) @ wqt_hi^T, 2-pass, hi-only out
    gemm_mma<3, 2><<<dim3(2, 2, NB), 256, SMEM_BYTES>>>(
        u_hi, u_lo, (long)CD * KD, wqt_hi, 0L,
        nullptr, weff_hi, nullptr, (long)CD * KD, KD, nullptr);

    // 6) y = weff_hi @ xt_hi^T + b_out, 1-pass
    gemm_mma<0, 1><<<dim3(NPIX / 128, 2, NB), 256, SMEM_BYTES>>>(
        weff_hi, nullptr, (long)CD * KD, xt_hi, (long)NPIX * CD,
        y, nullptr, nullptr, (long)CD * NPIX, NPIX, b_out);
}